// round 5
// baseline (speedup 1.0000x reference)
#include <cuda_runtime.h>

#define FULLMASK 0xffffffffu
#define MINV 1e-12f
#define EPSV 1e-6f
#define MAXN (1.0f - 1e-5f)
#define KPI  (1.0f/0.66f)

#define NWARP 25
#define NTHR  (NWARP*32)

// shared layout (float offsets)
#define OFF_W4    0            // [2][64][128] packed lin_w
#define OFF_FW1T  16384        // [64][128]
#define OFF_FW2T  24576        // [128][128]
#define OFF_CONST 40960        // 912 floats
#define OFF_STAGE 41872
#define WSTRIDE   544
#define SOFF_WKM  512
#define SOFF_AARR 528
#define SOFF_MASK 532
#define SMEM_FLOATS (OFF_STAGE + NWARP*WSTRIDE)
#define SMEM_BYTES  (SMEM_FLOATS*4)

__device__ float g_const[1024];
// 0 klp[4][64], 256 hb[4][64], 512 fb1h[128], 640 fb2h[128], 768 gb1h[64], 832 gb2h[64], 896 scal[12]

__device__ __forceinline__ float wred(float v){
    v += __shfl_xor_sync(FULLMASK, v, 16);
    v += __shfl_xor_sync(FULLMASK, v, 8);
    v += __shfl_xor_sync(FULLMASK, v, 4);
    v += __shfl_xor_sync(FULLMASK, v, 2);
    v += __shfl_xor_sync(FULLMASK, v, 1);
    return v;
}
__device__ __forceinline__ float tanh_pos(float xx){
    float e = __expf(-2.0f*xx);
    return __fdividef(1.0f - e, 1.0f + e);
}
__device__ __forceinline__ float artanh_c(float xx){
    xx = fminf(fmaxf(xx, -1.0f + EPSV), 1.0f - EPSV);
    return 0.5f*__logf(__fdividef(1.0f + xx, 1.0f - xx));
}
__device__ __forceinline__ float f4get(const float4 v, int i){
    return (i==0) ? v.x : (i==1) ? v.y : (i==2) ? v.z : v.w;
}

template<int V>
__device__ __forceinline__ void emap(const float* __restrict__ b, float* __restrict__ dst,
                                     float* __restrict__ n2dst, bool doproj){
    int l = threadIdx.x & 31;
    float u[V]; float s = 0.f;
    #pragma unroll
    for (int c=0;c<V;c++){ u[c] = b[V*l+c]; s += u[c]*u[c]; }
    float n2 = wred(s);
    float n  = sqrtf(fmaxf(n2, MINV));
    float f  = __fdividef(tanh_pos(n), n);
    float h2 = f*f*n2;
    if (doproj){
        float pn = sqrtf(fmaxf(h2, MINV));
        if (pn > MAXN){ f *= __fdividef(MAXN, pn); h2 = MAXN*MAXN; }
    }
    #pragma unroll
    for (int c=0;c<V;c++) dst[V*l+c] = f*u[c];
    if (l == 0) *n2dst = h2;
}

__global__ void prep_kernel(const float* __restrict__ kt, const float* __restrict__ lin_b,
                            const float* __restrict__ fb1, const float* __restrict__ fb2,
                            const float* __restrict__ gb1, const float* __restrict__ gb2){
    int w = threadIdx.x >> 5;
    if (w < 4){
        emap<2>(kt + w*64,    g_const + w*64,       g_const + 896 + w, false);
        emap<2>(lin_b + w*64, g_const + 256 + w*64, g_const + 900 + w, true);
    } else if (w == 4) emap<4>(fb1, g_const + 512, g_const + 904, true);
    else if (w == 5)   emap<4>(fb2, g_const + 640, g_const + 905, true);
    else if (w == 6)   emap<2>(gb1, g_const + 768, g_const + 906, true);
    else if (w == 7)   emap<2>(gb2, g_const + 832, g_const + 907, true);
}

template<int V>
__device__ __forceinline__ void blin_nl(float* h, const float* bvec, float b2,
                                        float ax_in, bool do_act,
                                        float& out_ax, float& out_n2){
    float s = 0.f;
    #pragma unroll
    for (int c=0;c<V;c++) s += h[c]*h[c];
    float mv2 = wred(s);
    float mvn = sqrtf(fmaxf(mv2, MINV));
    float fac = __fdividef(tanh_pos(mvn*ax_in), mvn);
    float f2  = fac*fac*mv2;
    { float pn = sqrtf(fmaxf(f2, MINV));
      if (pn > MAXN){ fac *= __fdividef(MAXN, pn); f2 = MAXN*MAXN; } }
    float mh = 0.f;
    #pragma unroll
    for (int c=0;c<V;c++) mh += h[c]*bvec[c];
    mh = wred(mh);
    float xy  = fac*mh;
    float A   = 1.0f + 2.0f*xy + b2;
    float B   = 1.0f - f2;
    float D   = fmaxf(1.0f + 2.0f*xy + f2*b2, MINV);
    float idn = __fdividef(1.0f, D);
    float r2  = (A*A*f2 + 2.0f*A*B*xy + B*B*b2)*idn*idn;
    float sp  = 1.0f;
    { float rn = sqrtf(fmaxf(r2, MINV));
      if (rn > MAXN){ sp = __fdividef(MAXN, rn); r2 = MAXN*MAXN; } }
    float cA = sp*idn*A*fac, cB = sp*idn*B;
    #pragma unroll
    for (int c=0;c<V;c++) h[c] = cA*h[c] + cB*bvec[c];
    if (do_act){
        float rn = sqrtf(fmaxf(r2, MINV));
        float lm = __fdividef(artanh_c(rn), rn);
        float t = 0.f;
        #pragma unroll
        for (int c=0;c<V;c++){ float u = fmaxf(h[c],0.f)*lm; h[c]=u; t += u*u; }
        float t2 = wred(t);
        float tn = sqrtf(fmaxf(t2, MINV));
        float ef = __fdividef(tanh_pos(tn), tn);
        float o2 = ef*ef*t2;
        float so = 1.0f;
        { float on = sqrtf(fmaxf(o2, MINV));
          if (on > MAXN){ so = __fdividef(MAXN, on); o2 = MAXN*MAXN; } }
        float cc = ef*so;
        #pragma unroll
        for (int c=0;c<V;c++) h[c] *= cc;
        r2 = o2;
    }
    out_n2 = r2;
    float nn = sqrtf(fmaxf(r2, MINV));
    out_ax = __fdividef(artanh_c(nn), nn);
}

__global__ void __launch_bounds__(NTHR, 1)
kp_main(const float* __restrict__ x, const int* __restrict__ nei,
        const float* __restrict__ neimask, const float* __restrict__ lin_w,
        const float* __restrict__ fw1, const float* __restrict__ fw2,
        const float* __restrict__ gw1, const float* __restrict__ gw2,
        float* __restrict__ out, int N)
{
    extern __shared__ float sm[];
    const int tid = threadIdx.x, wid = tid >> 5, l = tid & 31;

    for (int i = tid; i < 16384; i += NTHR){
        int p = i >> 13, r = i & 8191, row = r >> 7, q = r & 127;
        int lane = q >> 2, c = q & 3;
        int k = 2*p + (c >> 1), o = 2*lane + (c & 1);
        sm[OFF_W4 + i] = lin_w[k*4096 + o*64 + row];
    }
    for (int i = tid; i < 8192; i += NTHR){
        int o = i >> 6, ii = i & 63;
        sm[OFF_FW1T + ii*128 + o] = fw1[i];
    }
    for (int i = tid; i < 16384; i += NTHR){
        int o = i >> 7, ii = i & 127;
        sm[OFF_FW2T + ii*128 + o] = fw2[i];
    }
    for (int i = tid; i < 908; i += NTHR) sm[OFF_CONST + i] = g_const[i];
    __syncthreads();

    const int node = blockIdx.x*NWARP + wid;
    if (node >= N) return;

    float* S = sm + OFF_STAGE + wid*WSTRIDE;
    const float* KLP  = sm + OFF_CONST;
    const float* HB   = KLP + 256;
    const float* FB1H = KLP + 512;
    const float* FB2H = KLP + 640;
    const float* GB1H = KLP + 768;
    const float* GB2H = KLP + 832;
    const float* SC   = KLP + 896;

    // center point
    float2 xv = *(const float2*)(x + node*64 + 2*l);
    float x2 = wred(xv.x*xv.x + xv.y*xv.y);
    { float n = sqrtf(fmaxf(x2, MINV));
      if (n > MAXN){ float s = __fdividef(MAXN, n); xv.x*=s; xv.y*=s; x2 = MAXN*MAXN; } }

    // kernel points resident in registers; center-kernel dots hoisted (node-invariant)
    float2 kp0 = *(const float2*)(KLP + 0*64 + 2*l);
    float2 kp1 = *(const float2*)(KLP + 1*64 + 2*l);
    float2 kp2 = *(const float2*)(KLP + 2*64 + 2*l);
    float2 kp3 = *(const float2*)(KLP + 3*64 + 2*l);
    float xk[4];
    xk[0] = wred(xv.x*kp0.x + xv.y*kp0.y);
    xk[1] = wred(xv.x*kp1.x + xv.y*kp1.y);
    xk[2] = wred(xv.x*kp2.x + xv.y*kp2.y);
    xk[3] = wred(xv.x*kp3.x + xv.y*kp3.y);

    float mnum[4] = {0.f,0.f,0.f,0.f};
    float mden = 0.f;

    for (int g = 0; g < 4; g++){
        // ---- stage A: gather/proj neighbors, KP correlation weights ----
        #pragma unroll
        for (int mm=0; mm<4; mm++){
            const int m = g*4 + mm;
            const int idx = __ldg(nei + node*16 + m);
            float mk = __ldg(neimask + node*16 + m);
            float2 v = *(const float2*)(x + idx*64 + 2*l);
            float n2 = wred(v.x*v.x + v.y*v.y);
            float nn = sqrtf(fmaxf(n2, MINV));
            if (nn > MAXN){ float s = __fdividef(MAXN, nn); v.x*=s; v.y*=s; n2 = MAXN*MAXN; nn = MAXN; }
            float aa = __fdividef(artanh_c(nn), nn);
            *(float2*)(S + mm*64 + 2*l) = v;
            float xdn = wred(xv.x*v.x + xv.y*v.y);
            float nk[4];
            nk[0] = wred(v.x*kp0.x + v.y*kp0.y);
            nk[1] = wred(v.x*kp1.x + v.y*kp1.y);
            nk[2] = wred(v.x*kp2.x + v.y*kp2.y);
            nk[3] = wred(v.x*kp3.x + v.y*kp3.y);
            float a   = 1.0f - 2.0f*xdn + n2;
            float b   = 1.0f - x2;
            float den = fmaxf(1.0f - 2.0f*xdn + x2*n2, MINV);
            float idn = __fdividef(1.0f, den);
            float x02 = (a*a*x2 - 2.0f*a*b*xdn + b*b*n2)*idn*idn;
            float s0  = 1.0f;
            { float n0 = sqrtf(fmaxf(x02, MINV));
              if (n0 > MAXN){ s0 = __fdividef(MAXN, n0); x02 = MAXN*MAXN; } }
            float wv[4]; float sw = 0.f;
            #pragma unroll
            for (int k=0;k<4;k++){
                float klp2 = SC[k];
                float x0k = (-a*xk[k] + b*nk[k])*idn*s0;
                float A = 1.0f - 2.0f*x0k + klp2;
                float B = 1.0f - x02;
                float D = fmaxf(1.0f - 2.0f*x0k + x02*klp2, MINV);
                float iD = __fdividef(1.0f, D);
                float nsq = (A*A*x02 - 2.0f*A*B*x0k + B*B*klp2)*iD*iD;
                float nd = sqrtf(fmaxf(nsq, MINV));
                float d  = 2.0f*artanh_c(nd);
                wv[k] = fmaxf(0.f, 1.0f - d*KPI);
                sw += wv[k];
            }
            float isw = __fdividef(1.0f, fmaxf(sw, MINV));
            if (l == 0){
                #pragma unroll
                for (int k=0;k<4;k++) S[SOFF_WKM + mm*4 + k] = wv[k]*isw;
                S[SOFF_AARR + mm] = aa;
                S[SOFF_MASK + mm] = mk;
            }
        }
        __syncwarp();

        // ---- stage B: two k-pair passes, epilogue accumulates Klein sums per mm ----
        float kn0[4], kn1[4], kdn[4];
        #pragma unroll
        for (int mm=0;mm<4;mm++){ kn0[mm]=0.f; kn1[mm]=0.f; kdn[mm]=0.f; }
        #pragma unroll 1
        for (int p=0;p<2;p++){
            float acc[2][4][2];
            #pragma unroll
            for (int kk=0;kk<2;kk++)
                #pragma unroll
                for (int mm=0;mm<4;mm++){ acc[kk][mm][0]=0.f; acc[kk][mm][1]=0.f; }
            #pragma unroll 2
            for (int j4=0;j4<16;j4++){
                float4 xq0 = *(const float4*)(S + 0*64 + j4*4);
                float4 xq1 = *(const float4*)(S + 1*64 + j4*4);
                float4 xq2 = *(const float4*)(S + 2*64 + j4*4);
                float4 xq3 = *(const float4*)(S + 3*64 + j4*4);
                #pragma unroll
                for (int jj=0;jj<4;jj++){
                    float4 w4 = *(const float4*)(sm + OFF_W4 + p*8192 + (j4*4+jj)*128 + 4*l);
                    float xa0=f4get(xq0,jj), xa1=f4get(xq1,jj), xa2=f4get(xq2,jj), xa3=f4get(xq3,jj);
                    acc[0][0][0] += w4.x*xa0; acc[0][0][1] += w4.y*xa0;
                    acc[1][0][0] += w4.z*xa0; acc[1][0][1] += w4.w*xa0;
                    acc[0][1][0] += w4.x*xa1; acc[0][1][1] += w4.y*xa1;
                    acc[1][1][0] += w4.z*xa1; acc[1][1][1] += w4.w*xa1;
                    acc[0][2][0] += w4.x*xa2; acc[0][2][1] += w4.y*xa2;
                    acc[1][2][0] += w4.z*xa2; acc[1][2][1] += w4.w*xa2;
                    acc[0][3][0] += w4.x*xa3; acc[0][3][1] += w4.y*xa3;
                    acc[1][3][0] += w4.z*xa3; acc[1][3][1] += w4.w*xa3;
                }
            }
            #pragma unroll
            for (int kk=0;kk<2;kk++){
                const int k = 2*p+kk;
                const float hb2k = SC[4+k];
                float2 hbv = *(const float2*)(HB + k*64 + 2*l);
                #pragma unroll
                for (int mm=0;mm<4;mm++){
                    float a0=acc[kk][mm][0], a1=acc[kk][mm][1];
                    float mx2 = wred(a0*a0 + a1*a1);
                    float mxn = sqrtf(fmaxf(mx2, MINV));
                    float aa  = S[SOFF_AARR + mm];
                    float fac = __fdividef(tanh_pos(mxn*aa), mxn);
                    float f2  = fac*fac*mx2;
                    { float pn = sqrtf(fmaxf(f2, MINV));
                      if (pn > MAXN){ fac *= __fdividef(MAXN, pn); f2 = MAXN*MAXN; } }
                    float mh = wred(a0*hbv.x + a1*hbv.y);
                    float xy = fac*mh;
                    float A = 1.0f + 2.0f*xy + hb2k;
                    float B = 1.0f - f2;
                    float D = fmaxf(1.0f + 2.0f*xy + f2*hb2k, MINV);
                    float iD = __fdividef(1.0f, D);
                    float r2 = (A*A*f2 + 2.0f*A*B*xy + B*B*hb2k)*iD*iD;
                    float sp = 1.0f;
                    { float rn = sqrtf(fmaxf(r2, MINV));
                      if (rn > MAXN){ sp = __fdividef(MAXN, rn); r2 = MAXN*MAXN; } }
                    float fk  = __fdividef(2.0f, 1.0f + r2);
                    float kk2 = fk*fk*r2;
                    float lor = rsqrtf(fmaxf(1.0f - kk2, MINV));
                    float cw  = S[SOFF_WKM + mm*4 + k]*lor;
                    float cf  = cw*fk*sp*iD;
                    kn0[mm] += cf*(A*fac*a0 + B*hbv.x);
                    kn1[mm] += cf*(A*fac*a1 + B*hbv.y);
                    kdn[mm] += cw;
                }
            }
        }
        __syncwarp();

        // ---- stage C: Klein midpoint normalize -> agg ----
        float axagg[4];
        #pragma unroll
        for (int mm=0;mm<4;mm++){
            float ikd = __fdividef(1.0f, fmaxf(kdn[mm], MINV));
            float k0 = kn0[mm]*ikd, k1 = kn1[mm]*ikd;
            float kk2 = wred(k0*k0 + k1*k1);
            float s2 = __fdividef(1.0f, 1.0f + sqrtf(fmaxf(1.0f - kk2, MINV)));
            float p0 = s2*k0, p1 = s2*k1;
            float p2 = s2*s2*kk2;
            float spp = 1.0f;
            { float pn = sqrtf(fmaxf(p2, MINV));
              if (pn > MAXN){ spp = __fdividef(MAXN, pn); p2 = MAXN*MAXN; } }
            p0 *= spp; p1 *= spp;
            { float nn = sqrtf(fmaxf(p2, MINV)); axagg[mm] = __fdividef(artanh_c(nn), nn); }
            *(float2*)(S + mm*64 + 2*l) = make_float2(p0, p1);
        }
        __syncwarp();

        // ---- stage D1: h1 = blinear(agg, fw1, fb1, relu) ----
        float h1[4][4];
        #pragma unroll
        for (int mm=0;mm<4;mm++)
            #pragma unroll
            for (int c=0;c<4;c++) h1[mm][c] = 0.f;
        #pragma unroll 2
        for (int j4=0;j4<16;j4++){
            float4 xq0 = *(const float4*)(S + 0*64 + j4*4);
            float4 xq1 = *(const float4*)(S + 1*64 + j4*4);
            float4 xq2 = *(const float4*)(S + 2*64 + j4*4);
            float4 xq3 = *(const float4*)(S + 3*64 + j4*4);
            #pragma unroll
            for (int jj=0;jj<4;jj++){
                float4 wv = *(const float4*)(sm + OFF_FW1T + (j4*4+jj)*128 + 4*l);
                float xa0=f4get(xq0,jj), xa1=f4get(xq1,jj), xa2=f4get(xq2,jj), xa3=f4get(xq3,jj);
                h1[0][0]+=wv.x*xa0; h1[0][1]+=wv.y*xa0; h1[0][2]+=wv.z*xa0; h1[0][3]+=wv.w*xa0;
                h1[1][0]+=wv.x*xa1; h1[1][1]+=wv.y*xa1; h1[1][2]+=wv.z*xa1; h1[1][3]+=wv.w*xa1;
                h1[2][0]+=wv.x*xa2; h1[2][1]+=wv.y*xa2; h1[2][2]+=wv.z*xa2; h1[2][3]+=wv.w*xa2;
                h1[3][0]+=wv.x*xa3; h1[3][1]+=wv.y*xa3; h1[3][2]+=wv.z*xa3; h1[3][3]+=wv.w*xa3;
            }
        }
        __syncwarp();
        float ax1[4];
        {
            float bv1[4] = {FB1H[4*l], FB1H[4*l+1], FB1H[4*l+2], FB1H[4*l+3]};
            const float fb1h2 = SC[8];
            #pragma unroll
            for (int mm=0;mm<4;mm++){
                float n2o;
                blin_nl<4>(h1[mm], bv1, fb1h2, axagg[mm], true, ax1[mm], n2o);
                *(float4*)(S + mm*128 + 4*l) = make_float4(h1[mm][0], h1[mm][1], h1[mm][2], h1[mm][3]);
            }
        }
        __syncwarp();

        // ---- stage D2: h2 = blinear(h1, fw2, fb2) + neighbor Klein accumulation ----
        float h2a[4][4];
        #pragma unroll
        for (int mm=0;mm<4;mm++)
            #pragma unroll
            for (int c=0;c<4;c++) h2a[mm][c] = 0.f;
        #pragma unroll 2
        for (int j4=0;j4<32;j4++){
            float4 xq0 = *(const float4*)(S + 0*128 + j4*4);
            float4 xq1 = *(const float4*)(S + 1*128 + j4*4);
            float4 xq2 = *(const float4*)(S + 2*128 + j4*4);
            float4 xq3 = *(const float4*)(S + 3*128 + j4*4);
            #pragma unroll
            for (int jj=0;jj<4;jj++){
                float4 wv = *(const float4*)(sm + OFF_FW2T + (j4*4+jj)*128 + 4*l);
                float xa0=f4get(xq0,jj), xa1=f4get(xq1,jj), xa2=f4get(xq2,jj), xa3=f4get(xq3,jj);
                h2a[0][0]+=wv.x*xa0; h2a[0][1]+=wv.y*xa0; h2a[0][2]+=wv.z*xa0; h2a[0][3]+=wv.w*xa0;
                h2a[1][0]+=wv.x*xa1; h2a[1][1]+=wv.y*xa1; h2a[1][2]+=wv.z*xa1; h2a[1][3]+=wv.w*xa1;
                h2a[2][0]+=wv.x*xa2; h2a[2][1]+=wv.y*xa2; h2a[2][2]+=wv.z*xa2; h2a[2][3]+=wv.w*xa2;
                h2a[3][0]+=wv.x*xa3; h2a[3][1]+=wv.y*xa3; h2a[3][2]+=wv.z*xa3; h2a[3][3]+=wv.w*xa3;
            }
        }
        {
            float bv2[4] = {FB2H[4*l], FB2H[4*l+1], FB2H[4*l+2], FB2H[4*l+3]};
            const float fb2h2 = SC[9];
            #pragma unroll
            for (int mm=0;mm<4;mm++){
                float axo, r2o;
                blin_nl<4>(h2a[mm], bv2, fb2h2, ax1[mm], false, axo, r2o);
                float fk  = __fdividef(2.0f, 1.0f + r2o);
                float kk2 = fk*fk*r2o;
                float lor = rsqrtf(fmaxf(1.0f - kk2, MINV));
                float cw  = S[SOFF_MASK + mm]*lor;
                float cf  = cw*fk;
                mden += cw;
                #pragma unroll
                for (int c=0;c<4;c++) mnum[c] += cf*h2a[mm][c];
            }
        }
        __syncwarp();
    }

    // ---- neighbor Klein midpoint -> mid (128-d) ----
    float imd = __fdividef(1.0f, fmaxf(mden, MINV));
    float mk4[4]; float s = 0.f;
    #pragma unroll
    for (int c=0;c<4;c++){ mk4[c] = mnum[c]*imd; s += mk4[c]*mk4[c]; }
    float kk2 = wred(s);
    float s2 = __fdividef(1.0f, 1.0f + sqrtf(fmaxf(1.0f - kk2, MINV)));
    float p2 = s2*s2*kk2;
    float spp = 1.0f;
    { float pn = sqrtf(fmaxf(p2, MINV));
      if (pn > MAXN){ spp = __fdividef(MAXN, pn); p2 = MAXN*MAXN; } }
    float cc = s2*spp;
    #pragma unroll
    for (int c=0;c<4;c++) mk4[c] *= cc;
    *(float4*)(S + 4*l) = make_float4(mk4[0], mk4[1], mk4[2], mk4[3]);
    float axmid;
    { float nn = sqrtf(fmaxf(p2, MINV)); axmid = __fdividef(artanh_c(nn), nn); }
    __syncwarp();

    // ---- tail E1: out1 = blinear(mid, gw1, gb1, relu) ----
    float g1v[2] = {0.f, 0.f};
    #pragma unroll 4
    for (int i4=0;i4<32;i4++){
        float4 xs = *(const float4*)(S + i4*4);
        float4 w0 = __ldg((const float4*)(gw1 + (2*l)*128 + i4*4));
        float4 w1 = __ldg((const float4*)(gw1 + (2*l+1)*128 + i4*4));
        g1v[0] += w0.x*xs.x + w0.y*xs.y + w0.z*xs.z + w0.w*xs.w;
        g1v[1] += w1.x*xs.x + w1.y*xs.y + w1.z*xs.z + w1.w*xs.w;
    }
    __syncwarp();
    float axo1, r2o1;
    {
        float bvg1[2] = {GB1H[2*l], GB1H[2*l+1]};
        blin_nl<2>(g1v, bvg1, SC[10], axmid, true, axo1, r2o1);
    }
    *(float2*)(S + 2*l) = make_float2(g1v[0], g1v[1]);
    __syncwarp();

    // ---- tail E2: out = blinear(out1, gw2, gb2) ----
    float g2v[2] = {0.f, 0.f};
    #pragma unroll 4
    for (int i4=0;i4<16;i4++){
        float4 xs = *(const float4*)(S + i4*4);
        float4 w0 = __ldg((const float4*)(gw2 + (2*l)*64 + i4*4));
        float4 w1 = __ldg((const float4*)(gw2 + (2*l+1)*64 + i4*4));
        g2v[0] += w0.x*xs.x + w0.y*xs.y + w0.z*xs.z + w0.w*xs.w;
        g2v[1] += w1.x*xs.x + w1.y*xs.y + w1.z*xs.z + w1.w*xs.w;
    }
    float axo2, r2o2;
    {
        float bvg2[2] = {GB2H[2*l], GB2H[2*l+1]};
        blin_nl<2>(g2v, bvg2, SC[11], axo1, false, axo2, r2o2);
    }
    *(float2*)(out + node*64 + 2*l) = make_float2(g2v[0], g2v[1]);
}

extern "C" void kernel_launch(void* const* d_in, const int* in_sizes, int n_in,
                              void* d_out, int out_size){
    const float* x       = (const float*)d_in[0];
    const int*   nei     = (const int*)  d_in[1];
    const float* neimask = (const float*)d_in[2];
    const float* kt      = (const float*)d_in[3];
    const float* lin_w   = (const float*)d_in[4];
    const float* lin_b   = (const float*)d_in[5];
    const float* fw1     = (const float*)d_in[6];
    const float* fb1     = (const float*)d_in[7];
    const float* fw2     = (const float*)d_in[8];
    const float* fb2     = (const float*)d_in[9];
    const float* gw1     = (const float*)d_in[10];
    const float* gb1     = (const float*)d_in[11];
    const float* gw2     = (const float*)d_in[12];
    const float* gb2     = (const float*)d_in[13];
    float* out = (float*)d_out;
    const int N = in_sizes[0]/64;

    cudaFuncSetAttribute(kp_main, cudaFuncAttributeMaxDynamicSharedMemorySize, SMEM_BYTES);
    prep_kernel<<<1, 256>>>(kt, lin_b, fb1, fb2, gb1, gb2);
    kp_main<<<(N + NWARP - 1)/NWARP, NTHR, SMEM_BYTES>>>(x, nei, neimask, lin_w, fw1, fw2, gw1, gw2, out, N);
}

// round 6
// speedup vs baseline: 1.1316x; 1.1316x over previous
#include <cuda_runtime.h>

#define FULLMASK 0xffffffffu
#define MINV 1e-12f
#define EPSV 1e-6f
#define MAXN (1.0f - 1e-5f)
#define KPI  (1.0f/0.66f)

#define NWARP 24
#define NTHR  (NWARP*32)

// shared layout (float offsets)
#define OFF_W4    0            // [2][64][128] packed lin_w
#define OFF_FW1T  16384        // [64][128]
#define OFF_FW2T  24576        // [128][128]
#define OFF_CONST 40960        // 912 floats
#define OFF_STAGE 41872
#define WSTRIDE   544
#define SOFF_WKM  512
#define SOFF_AARR 528
#define SOFF_MASK 532
#define SMEM_FLOATS (OFF_STAGE + NWARP*WSTRIDE)
#define SMEM_BYTES  (SMEM_FLOATS*4)

__device__ float g_const[1024];
// 0 klp[4][64], 256 hb[4][64], 512 fb1h[128], 640 fb2h[128], 768 gb1h[64], 832 gb2h[64], 896 scal[12]

__device__ __forceinline__ float wred(float v){
    v += __shfl_xor_sync(FULLMASK, v, 16);
    v += __shfl_xor_sync(FULLMASK, v, 8);
    v += __shfl_xor_sync(FULLMASK, v, 4);
    v += __shfl_xor_sync(FULLMASK, v, 2);
    v += __shfl_xor_sync(FULLMASK, v, 1);
    return v;
}
__device__ __forceinline__ float tanh_pos(float xx){
    float e = __expf(-2.0f*xx);
    return __fdividef(1.0f - e, 1.0f + e);
}
__device__ __forceinline__ float artanh_c(float xx){
    xx = fminf(fmaxf(xx, -1.0f + EPSV), 1.0f - EPSV);
    return 0.5f*__logf(__fdividef(1.0f + xx, 1.0f - xx));
}
__device__ __forceinline__ float f4get(const float4 v, int i){
    return (i==0) ? v.x : (i==1) ? v.y : (i==2) ? v.z : v.w;
}

template<int V>
__device__ __forceinline__ void emap(const float* __restrict__ b, float* __restrict__ dst,
                                     float* __restrict__ n2dst, bool doproj){
    int l = threadIdx.x & 31;
    float u[V]; float s = 0.f;
    #pragma unroll
    for (int c=0;c<V;c++){ u[c] = b[V*l+c]; s += u[c]*u[c]; }
    float n2 = wred(s);
    float n  = sqrtf(fmaxf(n2, MINV));
    float f  = __fdividef(tanh_pos(n), n);
    float h2 = f*f*n2;
    if (doproj){
        float pn = sqrtf(fmaxf(h2, MINV));
        if (pn > MAXN){ f *= __fdividef(MAXN, pn); h2 = MAXN*MAXN; }
    }
    #pragma unroll
    for (int c=0;c<V;c++) dst[V*l+c] = f*u[c];
    if (l == 0) *n2dst = h2;
}

__global__ void prep_kernel(const float* __restrict__ kt, const float* __restrict__ lin_b,
                            const float* __restrict__ fb1, const float* __restrict__ fb2,
                            const float* __restrict__ gb1, const float* __restrict__ gb2){
    int w = threadIdx.x >> 5;
    if (w < 4){
        emap<2>(kt + w*64,    g_const + w*64,       g_const + 896 + w, false);
        emap<2>(lin_b + w*64, g_const + 256 + w*64, g_const + 900 + w, true);
    } else if (w == 4) emap<4>(fb1, g_const + 512, g_const + 904, true);
    else if (w == 5)   emap<4>(fb2, g_const + 640, g_const + 905, true);
    else if (w == 6)   emap<2>(gb1, g_const + 768, g_const + 906, true);
    else if (w == 7)   emap<2>(gb2, g_const + 832, g_const + 907, true);
}

template<int V>
__device__ __forceinline__ void blin_nl(float* h, const float* bvec, float b2,
                                        float ax_in, bool do_act,
                                        float& out_ax, float& out_n2){
    float s = 0.f;
    #pragma unroll
    for (int c=0;c<V;c++) s += h[c]*h[c];
    float mv2 = wred(s);
    float mvn = sqrtf(fmaxf(mv2, MINV));
    float fac = __fdividef(tanh_pos(mvn*ax_in), mvn);
    float f2  = fac*fac*mv2;
    { float pn = sqrtf(fmaxf(f2, MINV));
      if (pn > MAXN){ fac *= __fdividef(MAXN, pn); f2 = MAXN*MAXN; } }
    float mh = 0.f;
    #pragma unroll
    for (int c=0;c<V;c++) mh += h[c]*bvec[c];
    mh = wred(mh);
    float xy  = fac*mh;
    float A   = 1.0f + 2.0f*xy + b2;
    float B   = 1.0f - f2;
    float D   = fmaxf(1.0f + 2.0f*xy + f2*b2, MINV);
    float idn = __fdividef(1.0f, D);
    float r2  = (A*A*f2 + 2.0f*A*B*xy + B*B*b2)*idn*idn;
    float sp  = 1.0f;
    { float rn = sqrtf(fmaxf(r2, MINV));
      if (rn > MAXN){ sp = __fdividef(MAXN, rn); r2 = MAXN*MAXN; } }
    float cA = sp*idn*A*fac, cB = sp*idn*B;
    #pragma unroll
    for (int c=0;c<V;c++) h[c] = cA*h[c] + cB*bvec[c];
    if (do_act){
        float rn = sqrtf(fmaxf(r2, MINV));
        float lm = __fdividef(artanh_c(rn), rn);
        float t = 0.f;
        #pragma unroll
        for (int c=0;c<V;c++){ float u = fmaxf(h[c],0.f)*lm; h[c]=u; t += u*u; }
        float t2 = wred(t);
        float tn = sqrtf(fmaxf(t2, MINV));
        float ef = __fdividef(tanh_pos(tn), tn);
        float o2 = ef*ef*t2;
        float so = 1.0f;
        { float on = sqrtf(fmaxf(o2, MINV));
          if (on > MAXN){ so = __fdividef(MAXN, on); o2 = MAXN*MAXN; } }
        float cc = ef*so;
        #pragma unroll
        for (int c=0;c<V;c++) h[c] *= cc;
        r2 = o2;
    }
    out_n2 = r2;
    float nn = sqrtf(fmaxf(r2, MINV));
    out_ax = __fdividef(artanh_c(nn), nn);
}

__global__ void __launch_bounds__(NTHR, 1)
kp_main(const float* __restrict__ x, const int* __restrict__ nei,
        const float* __restrict__ neimask, const float* __restrict__ lin_w,
        const float* __restrict__ fw1, const float* __restrict__ fw2,
        const float* __restrict__ gw1, const float* __restrict__ gw2,
        float* __restrict__ out, int N)
{
    extern __shared__ float sm[];
    const int tid = threadIdx.x, wid = tid >> 5, l = tid & 31;

    for (int i = tid; i < 16384; i += NTHR){
        int p = i >> 13, r = i & 8191, row = r >> 7, q = r & 127;
        int lane = q >> 2, c = q & 3;
        int k = 2*p + (c >> 1), o = 2*lane + (c & 1);
        sm[OFF_W4 + i] = lin_w[k*4096 + o*64 + row];
    }
    for (int i = tid; i < 8192; i += NTHR){
        int o = i >> 6, ii = i & 63;
        sm[OFF_FW1T + ii*128 + o] = fw1[i];
    }
    for (int i = tid; i < 16384; i += NTHR){
        int o = i >> 7, ii = i & 127;
        sm[OFF_FW2T + ii*128 + o] = fw2[i];
    }
    for (int i = tid; i < 908; i += NTHR) sm[OFF_CONST + i] = g_const[i];
    __syncthreads();

    const int node = blockIdx.x*NWARP + wid;
    if (node >= N) return;

    float* S = sm + OFF_STAGE + wid*WSTRIDE;
    const float* KLP  = sm + OFF_CONST;
    const float* HB   = KLP + 256;
    const float* FB1H = KLP + 512;
    const float* FB2H = KLP + 640;
    const float* GB1H = KLP + 768;
    const float* GB2H = KLP + 832;
    const float* SC   = KLP + 896;

    // center point
    float2 xv = *(const float2*)(x + node*64 + 2*l);
    float x2 = wred(xv.x*xv.x + xv.y*xv.y);
    { float n = sqrtf(fmaxf(x2, MINV));
      if (n > MAXN){ float s = __fdividef(MAXN, n); xv.x*=s; xv.y*=s; x2 = MAXN*MAXN; } }

    // center-kernel dots: node-invariant, hoisted out of the neighbor loop
    float xk[4];
    #pragma unroll
    for (int k=0;k<4;k++){
        float2 kp = *(const float2*)(KLP + k*64 + 2*l);
        xk[k] = wred(xv.x*kp.x + xv.y*kp.y);
    }

    float mnum[4] = {0.f,0.f,0.f,0.f};
    float mden = 0.f;

    for (int g = 0; g < 4; g++){
        // ---- stage A: gather/proj neighbors, KP correlation weights ----
        #pragma unroll
        for (int mm=0; mm<4; mm++){
            const int m = g*4 + mm;
            const int idx = __ldg(nei + node*16 + m);
            float mk = __ldg(neimask + node*16 + m);
            float2 v = *(const float2*)(x + idx*64 + 2*l);
            float n2 = wred(v.x*v.x + v.y*v.y);
            float nn = sqrtf(fmaxf(n2, MINV));
            if (nn > MAXN){ float s = __fdividef(MAXN, nn); v.x*=s; v.y*=s; n2 = MAXN*MAXN; nn = MAXN; }
            float aa = __fdividef(artanh_c(nn), nn);
            *(float2*)(S + mm*64 + 2*l) = v;
            float xdn = wred(xv.x*v.x + xv.y*v.y);
            float nk[4];
            #pragma unroll
            for (int k=0;k<4;k++){
                float2 kp = *(const float2*)(KLP + k*64 + 2*l);
                nk[k] = wred(v.x*kp.x + v.y*kp.y);
            }
            float a   = 1.0f - 2.0f*xdn + n2;
            float b   = 1.0f - x2;
            float den = fmaxf(1.0f - 2.0f*xdn + x2*n2, MINV);
            float idn = __fdividef(1.0f, den);
            float x02 = (a*a*x2 - 2.0f*a*b*xdn + b*b*n2)*idn*idn;
            float s0  = 1.0f;
            { float n0 = sqrtf(fmaxf(x02, MINV));
              if (n0 > MAXN){ s0 = __fdividef(MAXN, n0); x02 = MAXN*MAXN; } }
            float wv[4]; float sw = 0.f;
            #pragma unroll
            for (int k=0;k<4;k++){
                float klp2 = SC[k];
                float x0k = (-a*xk[k] + b*nk[k])*idn*s0;
                float A = 1.0f - 2.0f*x0k + klp2;
                float B = 1.0f - x02;
                float D = fmaxf(1.0f - 2.0f*x0k + x02*klp2, MINV);
                float iD = __fdividef(1.0f, D);
                float nsq = (A*A*x02 - 2.0f*A*B*x0k + B*B*klp2)*iD*iD;
                float nd = sqrtf(fmaxf(nsq, MINV));
                float d  = 2.0f*artanh_c(nd);
                wv[k] = fmaxf(0.f, 1.0f - d*KPI);
                sw += wv[k];
            }
            float isw = __fdividef(1.0f, fmaxf(sw, MINV));
            if (l == 0){
                #pragma unroll
                for (int k=0;k<4;k++) S[SOFF_WKM + mm*4 + k] = wv[k]*isw;
                S[SOFF_AARR + mm] = aa;
                S[SOFF_MASK + mm] = mk;
            }
        }
        __syncwarp();

        // ---- stage B: two k-pair passes, epilogue accumulates Klein sums per mm ----
        float kn0[4], kn1[4], kdn[4];
        #pragma unroll
        for (int mm=0;mm<4;mm++){ kn0[mm]=0.f; kn1[mm]=0.f; kdn[mm]=0.f; }
        #pragma unroll 1
        for (int p=0;p<2;p++){
            float acc[2][4][2];
            #pragma unroll
            for (int kk=0;kk<2;kk++)
                #pragma unroll
                for (int mm=0;mm<4;mm++){ acc[kk][mm][0]=0.f; acc[kk][mm][1]=0.f; }
            #pragma unroll 2
            for (int j4=0;j4<16;j4++){
                float4 xq0 = *(const float4*)(S + 0*64 + j4*4);
                float4 xq1 = *(const float4*)(S + 1*64 + j4*4);
                float4 xq2 = *(const float4*)(S + 2*64 + j4*4);
                float4 xq3 = *(const float4*)(S + 3*64 + j4*4);
                #pragma unroll
                for (int jj=0;jj<4;jj++){
                    float4 w4 = *(const float4*)(sm + OFF_W4 + p*8192 + (j4*4+jj)*128 + 4*l);
                    float xa0=f4get(xq0,jj), xa1=f4get(xq1,jj), xa2=f4get(xq2,jj), xa3=f4get(xq3,jj);
                    acc[0][0][0] += w4.x*xa0; acc[0][0][1] += w4.y*xa0;
                    acc[1][0][0] += w4.z*xa0; acc[1][0][1] += w4.w*xa0;
                    acc[0][1][0] += w4.x*xa1; acc[0][1][1] += w4.y*xa1;
                    acc[1][1][0] += w4.z*xa1; acc[1][1][1] += w4.w*xa1;
                    acc[0][2][0] += w4.x*xa2; acc[0][2][1] += w4.y*xa2;
                    acc[1][2][0] += w4.z*xa2; acc[1][2][1] += w4.w*xa2;
                    acc[0][3][0] += w4.x*xa3; acc[0][3][1] += w4.y*xa3;
                    acc[1][3][0] += w4.z*xa3; acc[1][3][1] += w4.w*xa3;
                }
            }
            #pragma unroll
            for (int kk=0;kk<2;kk++){
                const int k = 2*p+kk;
                const float hb2k = SC[4+k];
                float2 hbv = *(const float2*)(HB + k*64 + 2*l);
                #pragma unroll
                for (int mm=0;mm<4;mm++){
                    float a0=acc[kk][mm][0], a1=acc[kk][mm][1];
                    float mx2 = wred(a0*a0 + a1*a1);
                    float mxn = sqrtf(fmaxf(mx2, MINV));
                    float aa  = S[SOFF_AARR + mm];
                    float fac = __fdividef(tanh_pos(mxn*aa), mxn);
                    float f2  = fac*fac*mx2;
                    { float pn = sqrtf(fmaxf(f2, MINV));
                      if (pn > MAXN){ fac *= __fdividef(MAXN, pn); f2 = MAXN*MAXN; } }
                    float mh = wred(a0*hbv.x + a1*hbv.y);
                    float xy = fac*mh;
                    float A = 1.0f + 2.0f*xy + hb2k;
                    float B = 1.0f - f2;
                    float D = fmaxf(1.0f + 2.0f*xy + f2*hb2k, MINV);
                    float iD = __fdividef(1.0f, D);
                    float r2 = (A*A*f2 + 2.0f*A*B*xy + B*B*hb2k)*iD*iD;
                    float sp = 1.0f;
                    { float rn = sqrtf(fmaxf(r2, MINV));
                      if (rn > MAXN){ sp = __fdividef(MAXN, rn); r2 = MAXN*MAXN; } }
                    float fk  = __fdividef(2.0f, 1.0f + r2);
                    float kk2 = fk*fk*r2;
                    float lor = rsqrtf(fmaxf(1.0f - kk2, MINV));
                    float cw  = S[SOFF_WKM + mm*4 + k]*lor;
                    float cf  = cw*fk*sp*iD;
                    kn0[mm] += cf*(A*fac*a0 + B*hbv.x);
                    kn1[mm] += cf*(A*fac*a1 + B*hbv.y);
                    kdn[mm] += cw;
                }
            }
        }
        __syncwarp();

        // ---- stage C: Klein midpoint normalize -> agg ----
        float axagg[4];
        #pragma unroll
        for (int mm=0;mm<4;mm++){
            float ikd = __fdividef(1.0f, fmaxf(kdn[mm], MINV));
            float k0 = kn0[mm]*ikd, k1 = kn1[mm]*ikd;
            float kk2 = wred(k0*k0 + k1*k1);
            float s2 = __fdividef(1.0f, 1.0f + sqrtf(fmaxf(1.0f - kk2, MINV)));
            float p0 = s2*k0, p1 = s2*k1;
            float p2 = s2*s2*kk2;
            float spp = 1.0f;
            { float pn = sqrtf(fmaxf(p2, MINV));
              if (pn > MAXN){ spp = __fdividef(MAXN, pn); p2 = MAXN*MAXN; } }
            p0 *= spp; p1 *= spp;
            { float nn = sqrtf(fmaxf(p2, MINV)); axagg[mm] = __fdividef(artanh_c(nn), nn); }
            *(float2*)(S + mm*64 + 2*l) = make_float2(p0, p1);
        }
        __syncwarp();

        // ---- stage D1: h1 = blinear(agg, fw1, fb1, relu) ----
        float h1[4][4];
        #pragma unroll
        for (int mm=0;mm<4;mm++)
            #pragma unroll
            for (int c=0;c<4;c++) h1[mm][c] = 0.f;
        #pragma unroll 2
        for (int j4=0;j4<16;j4++){
            float4 xq0 = *(const float4*)(S + 0*64 + j4*4);
            float4 xq1 = *(const float4*)(S + 1*64 + j4*4);
            float4 xq2 = *(const float4*)(S + 2*64 + j4*4);
            float4 xq3 = *(const float4*)(S + 3*64 + j4*4);
            #pragma unroll
            for (int jj=0;jj<4;jj++){
                float4 wv = *(const float4*)(sm + OFF_FW1T + (j4*4+jj)*128 + 4*l);
                float xa0=f4get(xq0,jj), xa1=f4get(xq1,jj), xa2=f4get(xq2,jj), xa3=f4get(xq3,jj);
                h1[0][0]+=wv.x*xa0; h1[0][1]+=wv.y*xa0; h1[0][2]+=wv.z*xa0; h1[0][3]+=wv.w*xa0;
                h1[1][0]+=wv.x*xa1; h1[1][1]+=wv.y*xa1; h1[1][2]+=wv.z*xa1; h1[1][3]+=wv.w*xa1;
                h1[2][0]+=wv.x*xa2; h1[2][1]+=wv.y*xa2; h1[2][2]+=wv.z*xa2; h1[2][3]+=wv.w*xa2;
                h1[3][0]+=wv.x*xa3; h1[3][1]+=wv.y*xa3; h1[3][2]+=wv.z*xa3; h1[3][3]+=wv.w*xa3;
            }
        }
        __syncwarp();
        float ax1[4];
        {
            float bv1[4] = {FB1H[4*l], FB1H[4*l+1], FB1H[4*l+2], FB1H[4*l+3]};
            const float fb1h2 = SC[8];
            #pragma unroll
            for (int mm=0;mm<4;mm++){
                float n2o;
                blin_nl<4>(h1[mm], bv1, fb1h2, axagg[mm], true, ax1[mm], n2o);
                *(float4*)(S + mm*128 + 4*l) = make_float4(h1[mm][0], h1[mm][1], h1[mm][2], h1[mm][3]);
            }
        }
        __syncwarp();

        // ---- stage D2: h2 = blinear(h1, fw2, fb2) + neighbor Klein accumulation ----
        float h2a[4][4];
        #pragma unroll
        for (int mm=0;mm<4;mm++)
            #pragma unroll
            for (int c=0;c<4;c++) h2a[mm][c] = 0.f;
        #pragma unroll 2
        for (int j4=0;j4<32;j4++){
            float4 xq0 = *(const float4*)(S + 0*128 + j4*4);
            float4 xq1 = *(const float4*)(S + 1*128 + j4*4);
            float4 xq2 = *(const float4*)(S + 2*128 + j4*4);
            float4 xq3 = *(const float4*)(S + 3*128 + j4*4);
            #pragma unroll
            for (int jj=0;jj<4;jj++){
                float4 wv = *(const float4*)(sm + OFF_FW2T + (j4*4+jj)*128 + 4*l);
                float xa0=f4get(xq0,jj), xa1=f4get(xq1,jj), xa2=f4get(xq2,jj), xa3=f4get(xq3,jj);
                h2a[0][0]+=wv.x*xa0; h2a[0][1]+=wv.y*xa0; h2a[0][2]+=wv.z*xa0; h2a[0][3]+=wv.w*xa0;
                h2a[1][0]+=wv.x*xa1; h2a[1][1]+=wv.y*xa1; h2a[1][2]+=wv.z*xa1; h2a[1][3]+=wv.w*xa1;
                h2a[2][0]+=wv.x*xa2; h2a[2][1]+=wv.y*xa2; h2a[2][2]+=wv.z*xa2; h2a[2][3]+=wv.w*xa2;
                h2a[3][0]+=wv.x*xa3; h2a[3][1]+=wv.y*xa3; h2a[3][2]+=wv.z*xa3; h2a[3][3]+=wv.w*xa3;
            }
        }
        {
            float bv2[4] = {FB2H[4*l], FB2H[4*l+1], FB2H[4*l+2], FB2H[4*l+3]};
            const float fb2h2 = SC[9];
            #pragma unroll
            for (int mm=0;mm<4;mm++){
                float axo, r2o;
                blin_nl<4>(h2a[mm], bv2, fb2h2, ax1[mm], false, axo, r2o);
                float fk  = __fdividef(2.0f, 1.0f + r2o);
                float kk2 = fk*fk*r2o;
                float lor = rsqrtf(fmaxf(1.0f - kk2, MINV));
                float cw  = S[SOFF_MASK + mm]*lor;
                float cf  = cw*fk;
                mden += cw;
                #pragma unroll
                for (int c=0;c<4;c++) mnum[c] += cf*h2a[mm][c];
            }
        }
        __syncwarp();
    }

    // ---- neighbor Klein midpoint -> mid (128-d) ----
    float imd = __fdividef(1.0f, fmaxf(mden, MINV));
    float mk4[4]; float s = 0.f;
    #pragma unroll
    for (int c=0;c<4;c++){ mk4[c] = mnum[c]*imd; s += mk4[c]*mk4[c]; }
    float kk2 = wred(s);
    float s2 = __fdividef(1.0f, 1.0f + sqrtf(fmaxf(1.0f - kk2, MINV)));
    float p2 = s2*s2*kk2;
    float spp = 1.0f;
    { float pn = sqrtf(fmaxf(p2, MINV));
      if (pn > MAXN){ spp = __fdividef(MAXN, pn); p2 = MAXN*MAXN; } }
    float cc = s2*spp;
    #pragma unroll
    for (int c=0;c<4;c++) mk4[c] *= cc;
    *(float4*)(S + 4*l) = make_float4(mk4[0], mk4[1], mk4[2], mk4[3]);
    float axmid;
    { float nn = sqrtf(fmaxf(p2, MINV)); axmid = __fdividef(artanh_c(nn), nn); }
    __syncwarp();

    // ---- tail E1: out1 = blinear(mid, gw1, gb1, relu) ----
    float g1v[2] = {0.f, 0.f};
    #pragma unroll 4
    for (int i4=0;i4<32;i4++){
        float4 xs = *(const float4*)(S + i4*4);
        float4 w0 = __ldg((const float4*)(gw1 + (2*l)*128 + i4*4));
        float4 w1 = __ldg((const float4*)(gw1 + (2*l+1)*128 + i4*4));
        g1v[0] += w0.x*xs.x + w0.y*xs.y + w0.z*xs.z + w0.w*xs.w;
        g1v[1] += w1.x*xs.x + w1.y*xs.y + w1.z*xs.z + w1.w*xs.w;
    }
    __syncwarp();
    float axo1, r2o1;
    {
        float bvg1[2] = {GB1H[2*l], GB1H[2*l+1]};
        blin_nl<2>(g1v, bvg1, SC[10], axmid, true, axo1, r2o1);
    }
    *(float2*)(S + 2*l) = make_float2(g1v[0], g1v[1]);
    __syncwarp();

    // ---- tail E2: out = blinear(out1, gw2, gb2) ----
    float g2v[2] = {0.f, 0.f};
    #pragma unroll 4
    for (int i4=0;i4<16;i4++){
        float4 xs = *(const float4*)(S + i4*4);
        float4 w0 = __ldg((const float4*)(gw2 + (2*l)*64 + i4*4));
        float4 w1 = __ldg((const float4*)(gw2 + (2*l+1)*64 + i4*4));
        g2v[0] += w0.x*xs.x + w0.y*xs.y + w0.z*xs.z + w0.w*xs.w;
        g2v[1] += w1.x*xs.x + w1.y*xs.y + w1.z*xs.z + w1.w*xs.w;
    }
    float axo2, r2o2;
    {
        float bvg2[2] = {GB2H[2*l], GB2H[2*l+1]};
        blin_nl<2>(g2v, bvg2, SC[11], axo1, false, axo2, r2o2);
    }
    *(float2*)(out + node*64 + 2*l) = make_float2(g2v[0], g2v[1]);
}

extern "C" void kernel_launch(void* const* d_in, const int* in_sizes, int n_in,
                              void* d_out, int out_size){
    const float* x       = (const float*)d_in[0];
    const int*   nei     = (const int*)  d_in[1];
    const float* neimask = (const float*)d_in[2];
    const float* kt      = (const float*)d_in[3];
    const float* lin_w   = (const float*)d_in[4];
    const float* lin_b   = (const float*)d_in[5];
    const float* fw1     = (const float*)d_in[6];
    const float* fb1     = (const float*)d_in[7];
    const float* fw2     = (const float*)d_in[8];
    const float* fb2     = (const float*)d_in[9];
    const float* gw1     = (const float*)d_in[10];
    const float* gb1     = (const float*)d_in[11];
    const float* gw2     = (const float*)d_in[12];
    const float* gb2     = (const float*)d_in[13];
    float* out = (float*)d_out;
    const int N = in_sizes[0]/64;

    cudaFuncSetAttribute(kp_main, cudaFuncAttributeMaxDynamicSharedMemorySize, SMEM_BYTES);
    prep_kernel<<<1, 256>>>(kt, lin_b, fb1, fb2, gb1, gb2);
    kp_main<<<(N + NWARP - 1)/NWARP, NTHR, SMEM_BYTES>>>(x, nei, neimask, lin_w, fw1, fw2, gw1, gw2, out, N);
}

// round 7
// speedup vs baseline: 1.2327x; 1.0894x over previous
#include <cuda_runtime.h>

#define FULLMASK 0xffffffffu
#define MINV 1e-12f
#define EPSV 1e-6f
#define MAXN (1.0f - 1e-5f)
#define KPI  (1.0f/0.66f)

#define NWARP 28
#define NTHR  (NWARP*32)

// shared layout (float offsets)
#define OFF_W4    0            // [2][64][128] packed lin_w
#define OFF_FW1T  16384        // [64][128]
#define OFF_FW2T  24576        // [128][128]
#define OFF_CONST 40960        // 912 floats
#define OFF_STAGE 41872
#define WSTRIDE   544
#define SOFF_WKM  512
#define SOFF_AARR 528
#define SOFF_MASK 532
#define SMEM_FLOATS (OFF_STAGE + NWARP*WSTRIDE)
#define SMEM_BYTES  (SMEM_FLOATS*4)

__device__ float g_const[1024];
// 0 klp[4][64], 256 hb[4][64], 512 fb1h[128], 640 fb2h[128], 768 gb1h[64], 832 gb2h[64], 896 scal[12]

__device__ __forceinline__ float wred(float v){
    v += __shfl_xor_sync(FULLMASK, v, 16);
    v += __shfl_xor_sync(FULLMASK, v, 8);
    v += __shfl_xor_sync(FULLMASK, v, 4);
    v += __shfl_xor_sync(FULLMASK, v, 2);
    v += __shfl_xor_sync(FULLMASK, v, 1);
    return v;
}
__device__ __forceinline__ float tanh_pos(float xx){
    float e = __expf(-2.0f*xx);
    return __fdividef(1.0f - e, 1.0f + e);
}
__device__ __forceinline__ float artanh_c(float xx){
    xx = fminf(fmaxf(xx, -1.0f + EPSV), 1.0f - EPSV);
    return 0.5f*__logf(__fdividef(1.0f + xx, 1.0f - xx));
}
__device__ __forceinline__ float f4get(const float4 v, int i){
    return (i==0) ? v.x : (i==1) ? v.y : (i==2) ? v.z : v.w;
}

template<int V>
__device__ __forceinline__ void emap(const float* __restrict__ b, float* __restrict__ dst,
                                     float* __restrict__ n2dst, bool doproj){
    int l = threadIdx.x & 31;
    float u[V]; float s = 0.f;
    #pragma unroll
    for (int c=0;c<V;c++){ u[c] = b[V*l+c]; s += u[c]*u[c]; }
    float n2 = wred(s);
    float n  = sqrtf(fmaxf(n2, MINV));
    float f  = __fdividef(tanh_pos(n), n);
    float h2 = f*f*n2;
    if (doproj){
        float pn = sqrtf(fmaxf(h2, MINV));
        if (pn > MAXN){ f *= __fdividef(MAXN, pn); h2 = MAXN*MAXN; }
    }
    #pragma unroll
    for (int c=0;c<V;c++) dst[V*l+c] = f*u[c];
    if (l == 0) *n2dst = h2;
}

__global__ void prep_kernel(const float* __restrict__ kt, const float* __restrict__ lin_b,
                            const float* __restrict__ fb1, const float* __restrict__ fb2,
                            const float* __restrict__ gb1, const float* __restrict__ gb2){
    int w = threadIdx.x >> 5;
    if (w < 4){
        emap<2>(kt + w*64,    g_const + w*64,       g_const + 896 + w, false);
        emap<2>(lin_b + w*64, g_const + 256 + w*64, g_const + 900 + w, true);
    } else if (w == 4) emap<4>(fb1, g_const + 512, g_const + 904, true);
    else if (w == 5)   emap<4>(fb2, g_const + 640, g_const + 905, true);
    else if (w == 6)   emap<2>(gb1, g_const + 768, g_const + 906, true);
    else if (w == 7)   emap<2>(gb2, g_const + 832, g_const + 907, true);
}

template<int V>
__device__ __forceinline__ void blin_nl(float* h, const float* bvec, float b2,
                                        float ax_in, bool do_act,
                                        float& out_ax, float& out_n2){
    float s = 0.f;
    #pragma unroll
    for (int c=0;c<V;c++) s += h[c]*h[c];
    float mv2 = wred(s);
    float mvn = sqrtf(fmaxf(mv2, MINV));
    float fac = __fdividef(tanh_pos(mvn*ax_in), mvn);
    float f2  = fac*fac*mv2;
    { float pn = sqrtf(fmaxf(f2, MINV));
      if (pn > MAXN){ fac *= __fdividef(MAXN, pn); f2 = MAXN*MAXN; } }
    float mh = 0.f;
    #pragma unroll
    for (int c=0;c<V;c++) mh += h[c]*bvec[c];
    mh = wred(mh);
    float xy  = fac*mh;
    float A   = 1.0f + 2.0f*xy + b2;
    float B   = 1.0f - f2;
    float D   = fmaxf(1.0f + 2.0f*xy + f2*b2, MINV);
    float idn = __fdividef(1.0f, D);
    float r2  = (A*A*f2 + 2.0f*A*B*xy + B*B*b2)*idn*idn;
    float sp  = 1.0f;
    { float rn = sqrtf(fmaxf(r2, MINV));
      if (rn > MAXN){ sp = __fdividef(MAXN, rn); r2 = MAXN*MAXN; } }
    float cA = sp*idn*A*fac, cB = sp*idn*B;
    #pragma unroll
    for (int c=0;c<V;c++) h[c] = cA*h[c] + cB*bvec[c];
    if (do_act){
        float rn = sqrtf(fmaxf(r2, MINV));
        float lm = __fdividef(artanh_c(rn), rn);
        float t = 0.f;
        #pragma unroll
        for (int c=0;c<V;c++){ float u = fmaxf(h[c],0.f)*lm; h[c]=u; t += u*u; }
        float t2 = wred(t);
        float tn = sqrtf(fmaxf(t2, MINV));
        float ef = __fdividef(tanh_pos(tn), tn);
        float o2 = ef*ef*t2;
        float so = 1.0f;
        { float on = sqrtf(fmaxf(o2, MINV));
          if (on > MAXN){ so = __fdividef(MAXN, on); o2 = MAXN*MAXN; } }
        float cc = ef*so;
        #pragma unroll
        for (int c=0;c<V;c++) h[c] *= cc;
        r2 = o2;
    }
    out_n2 = r2;
    float nn = sqrtf(fmaxf(r2, MINV));
    out_ax = __fdividef(artanh_c(nn), nn);
}

__global__ void __launch_bounds__(NTHR, 1)
kp_main(const float* __restrict__ x, const int* __restrict__ nei,
        const float* __restrict__ neimask, const float* __restrict__ lin_w,
        const float* __restrict__ fw1, const float* __restrict__ fw2,
        const float* __restrict__ gw1, const float* __restrict__ gw2,
        float* __restrict__ out, int N)
{
    extern __shared__ float sm[];
    const int tid = threadIdx.x, wid = tid >> 5, l = tid & 31;

    for (int i = tid; i < 16384; i += NTHR){
        int p = i >> 13, r = i & 8191, row = r >> 7, q = r & 127;
        int lane = q >> 2, c = q & 3;
        int k = 2*p + (c >> 1), o = 2*lane + (c & 1);
        sm[OFF_W4 + i] = lin_w[k*4096 + o*64 + row];
    }
    for (int i = tid; i < 8192; i += NTHR){
        int o = i >> 6, ii = i & 63;
        sm[OFF_FW1T + ii*128 + o] = fw1[i];
    }
    for (int i = tid; i < 16384; i += NTHR){
        int o = i >> 7, ii = i & 127;
        sm[OFF_FW2T + ii*128 + o] = fw2[i];
    }
    for (int i = tid; i < 908; i += NTHR) sm[OFF_CONST + i] = g_const[i];
    __syncthreads();

    const int node = blockIdx.x*NWARP + wid;
    if (node >= N) return;

    float* S = sm + OFF_STAGE + wid*WSTRIDE;
    const float* KLP  = sm + OFF_CONST;
    const float* HB   = KLP + 256;
    const float* FB1H = KLP + 512;
    const float* FB2H = KLP + 640;
    const float* GB1H = KLP + 768;
    const float* GB2H = KLP + 832;
    const float* SC   = KLP + 896;

    // center point
    float2 xv = *(const float2*)(x + node*64 + 2*l);
    float x2 = wred(xv.x*xv.x + xv.y*xv.y);
    { float n = sqrtf(fmaxf(x2, MINV));
      if (n > MAXN){ float s = __fdividef(MAXN, n); xv.x*=s; xv.y*=s; x2 = MAXN*MAXN; } }

    // center-kernel dots: node-invariant, hoisted out of the neighbor loop
    float xk[4];
    #pragma unroll
    for (int k=0;k<4;k++){
        float2 kp = *(const float2*)(KLP + k*64 + 2*l);
        xk[k] = wred(xv.x*kp.x + xv.y*kp.y);
    }

    float mnum[4] = {0.f,0.f,0.f,0.f};
    float mden = 0.f;

    for (int g = 0; g < 4; g++){
        // ---- stage A: gather/proj neighbors, KP correlation weights ----
        #pragma unroll
        for (int mm=0; mm<4; mm++){
            const int m = g*4 + mm;
            const int idx = __ldg(nei + node*16 + m);
            float mk = __ldg(neimask + node*16 + m);
            float2 v = *(const float2*)(x + idx*64 + 2*l);
            float n2 = wred(v.x*v.x + v.y*v.y);
            float nn = sqrtf(fmaxf(n2, MINV));
            if (nn > MAXN){ float s = __fdividef(MAXN, nn); v.x*=s; v.y*=s; n2 = MAXN*MAXN; nn = MAXN; }
            float aa = __fdividef(artanh_c(nn), nn);
            *(float2*)(S + mm*64 + 2*l) = v;
            float xdn = wred(xv.x*v.x + xv.y*v.y);
            float nk[4];
            #pragma unroll
            for (int k=0;k<4;k++){
                float2 kp = *(const float2*)(KLP + k*64 + 2*l);
                nk[k] = wred(v.x*kp.x + v.y*kp.y);
            }
            float a   = 1.0f - 2.0f*xdn + n2;
            float b   = 1.0f - x2;
            float den = fmaxf(1.0f - 2.0f*xdn + x2*n2, MINV);
            float idn = __fdividef(1.0f, den);
            float x02 = (a*a*x2 - 2.0f*a*b*xdn + b*b*n2)*idn*idn;
            float s0  = 1.0f;
            { float n0 = sqrtf(fmaxf(x02, MINV));
              if (n0 > MAXN){ s0 = __fdividef(MAXN, n0); x02 = MAXN*MAXN; } }
            float wv[4]; float sw = 0.f;
            #pragma unroll
            for (int k=0;k<4;k++){
                float klp2 = SC[k];
                float x0k = (-a*xk[k] + b*nk[k])*idn*s0;
                float A = 1.0f - 2.0f*x0k + klp2;
                float B = 1.0f - x02;
                float D = fmaxf(1.0f - 2.0f*x0k + x02*klp2, MINV);
                float iD = __fdividef(1.0f, D);
                float nsq = (A*A*x02 - 2.0f*A*B*x0k + B*B*klp2)*iD*iD;
                float nd = sqrtf(fmaxf(nsq, MINV));
                float d  = 2.0f*artanh_c(nd);
                wv[k] = fmaxf(0.f, 1.0f - d*KPI);
                sw += wv[k];
            }
            float isw = __fdividef(1.0f, fmaxf(sw, MINV));
            if (l == 0){
                #pragma unroll
                for (int k=0;k<4;k++) S[SOFF_WKM + mm*4 + k] = wv[k]*isw;
                S[SOFF_AARR + mm] = aa;
                S[SOFF_MASK + mm] = mk;
            }
        }
        __syncwarp();

        // ---- stage B: two k-pair passes, epilogue accumulates Klein sums per mm ----
        float kn0[4], kn1[4], kdn[4];
        #pragma unroll
        for (int mm=0;mm<4;mm++){ kn0[mm]=0.f; kn1[mm]=0.f; kdn[mm]=0.f; }
        #pragma unroll 1
        for (int p=0;p<2;p++){
            float acc[2][4][2];
            #pragma unroll
            for (int kk=0;kk<2;kk++)
                #pragma unroll
                for (int mm=0;mm<4;mm++){ acc[kk][mm][0]=0.f; acc[kk][mm][1]=0.f; }
            #pragma unroll 2
            for (int j4=0;j4<16;j4++){
                float4 xq0 = *(const float4*)(S + 0*64 + j4*4);
                float4 xq1 = *(const float4*)(S + 1*64 + j4*4);
                float4 xq2 = *(const float4*)(S + 2*64 + j4*4);
                float4 xq3 = *(const float4*)(S + 3*64 + j4*4);
                #pragma unroll
                for (int jj=0;jj<4;jj++){
                    float4 w4 = *(const float4*)(sm + OFF_W4 + p*8192 + (j4*4+jj)*128 + 4*l);
                    float xa0=f4get(xq0,jj), xa1=f4get(xq1,jj), xa2=f4get(xq2,jj), xa3=f4get(xq3,jj);
                    acc[0][0][0] += w4.x*xa0; acc[0][0][1] += w4.y*xa0;
                    acc[1][0][0] += w4.z*xa0; acc[1][0][1] += w4.w*xa0;
                    acc[0][1][0] += w4.x*xa1; acc[0][1][1] += w4.y*xa1;
                    acc[1][1][0] += w4.z*xa1; acc[1][1][1] += w4.w*xa1;
                    acc[0][2][0] += w4.x*xa2; acc[0][2][1] += w4.y*xa2;
                    acc[1][2][0] += w4.z*xa2; acc[1][2][1] += w4.w*xa2;
                    acc[0][3][0] += w4.x*xa3; acc[0][3][1] += w4.y*xa3;
                    acc[1][3][0] += w4.z*xa3; acc[1][3][1] += w4.w*xa3;
                }
            }
            #pragma unroll
            for (int kk=0;kk<2;kk++){
                const int k = 2*p+kk;
                const float hb2k = SC[4+k];
                float2 hbv = *(const float2*)(HB + k*64 + 2*l);
                #pragma unroll
                for (int mm=0;mm<4;mm++){
                    float a0=acc[kk][mm][0], a1=acc[kk][mm][1];
                    float mx2 = wred(a0*a0 + a1*a1);
                    float mxn = sqrtf(fmaxf(mx2, MINV));
                    float aa  = S[SOFF_AARR + mm];
                    float fac = __fdividef(tanh_pos(mxn*aa), mxn);
                    float f2  = fac*fac*mx2;
                    { float pn = sqrtf(fmaxf(f2, MINV));
                      if (pn > MAXN){ fac *= __fdividef(MAXN, pn); f2 = MAXN*MAXN; } }
                    float mh = wred(a0*hbv.x + a1*hbv.y);
                    float xy = fac*mh;
                    float A = 1.0f + 2.0f*xy + hb2k;
                    float B = 1.0f - f2;
                    float D = fmaxf(1.0f + 2.0f*xy + f2*hb2k, MINV);
                    float iD = __fdividef(1.0f, D);
                    float r2 = (A*A*f2 + 2.0f*A*B*xy + B*B*hb2k)*iD*iD;
                    float sp = 1.0f;
                    { float rn = sqrtf(fmaxf(r2, MINV));
                      if (rn > MAXN){ sp = __fdividef(MAXN, rn); r2 = MAXN*MAXN; } }
                    float fk  = __fdividef(2.0f, 1.0f + r2);
                    float kk2 = fk*fk*r2;
                    float lor = rsqrtf(fmaxf(1.0f - kk2, MINV));
                    float cw  = S[SOFF_WKM + mm*4 + k]*lor;
                    float cf  = cw*fk*sp*iD;
                    kn0[mm] += cf*(A*fac*a0 + B*hbv.x);
                    kn1[mm] += cf*(A*fac*a1 + B*hbv.y);
                    kdn[mm] += cw;
                }
            }
        }
        __syncwarp();

        // ---- stage C: Klein midpoint normalize -> agg ----
        float axagg[4];
        #pragma unroll
        for (int mm=0;mm<4;mm++){
            float ikd = __fdividef(1.0f, fmaxf(kdn[mm], MINV));
            float k0 = kn0[mm]*ikd, k1 = kn1[mm]*ikd;
            float kk2 = wred(k0*k0 + k1*k1);
            float s2 = __fdividef(1.0f, 1.0f + sqrtf(fmaxf(1.0f - kk2, MINV)));
            float p0 = s2*k0, p1 = s2*k1;
            float p2 = s2*s2*kk2;
            float spp = 1.0f;
            { float pn = sqrtf(fmaxf(p2, MINV));
              if (pn > MAXN){ spp = __fdividef(MAXN, pn); p2 = MAXN*MAXN; } }
            p0 *= spp; p1 *= spp;
            { float nn = sqrtf(fmaxf(p2, MINV)); axagg[mm] = __fdividef(artanh_c(nn), nn); }
            *(float2*)(S + mm*64 + 2*l) = make_float2(p0, p1);
        }
        __syncwarp();

        // ---- stage D1: h1 = blinear(agg, fw1, fb1, relu) ----
        float h1[4][4];
        #pragma unroll
        for (int mm=0;mm<4;mm++)
            #pragma unroll
            for (int c=0;c<4;c++) h1[mm][c] = 0.f;
        #pragma unroll 2
        for (int j4=0;j4<16;j4++){
            float4 xq0 = *(const float4*)(S + 0*64 + j4*4);
            float4 xq1 = *(const float4*)(S + 1*64 + j4*4);
            float4 xq2 = *(const float4*)(S + 2*64 + j4*4);
            float4 xq3 = *(const float4*)(S + 3*64 + j4*4);
            #pragma unroll
            for (int jj=0;jj<4;jj++){
                float4 wv = *(const float4*)(sm + OFF_FW1T + (j4*4+jj)*128 + 4*l);
                float xa0=f4get(xq0,jj), xa1=f4get(xq1,jj), xa2=f4get(xq2,jj), xa3=f4get(xq3,jj);
                h1[0][0]+=wv.x*xa0; h1[0][1]+=wv.y*xa0; h1[0][2]+=wv.z*xa0; h1[0][3]+=wv.w*xa0;
                h1[1][0]+=wv.x*xa1; h1[1][1]+=wv.y*xa1; h1[1][2]+=wv.z*xa1; h1[1][3]+=wv.w*xa1;
                h1[2][0]+=wv.x*xa2; h1[2][1]+=wv.y*xa2; h1[2][2]+=wv.z*xa2; h1[2][3]+=wv.w*xa2;
                h1[3][0]+=wv.x*xa3; h1[3][1]+=wv.y*xa3; h1[3][2]+=wv.z*xa3; h1[3][3]+=wv.w*xa3;
            }
        }
        __syncwarp();
        float ax1[4];
        {
            float bv1[4] = {FB1H[4*l], FB1H[4*l+1], FB1H[4*l+2], FB1H[4*l+3]};
            const float fb1h2 = SC[8];
            #pragma unroll
            for (int mm=0;mm<4;mm++){
                float n2o;
                blin_nl<4>(h1[mm], bv1, fb1h2, axagg[mm], true, ax1[mm], n2o);
                *(float4*)(S + mm*128 + 4*l) = make_float4(h1[mm][0], h1[mm][1], h1[mm][2], h1[mm][3]);
            }
        }
        __syncwarp();

        // ---- stage D2: h2 = blinear(h1, fw2, fb2) + neighbor Klein accumulation ----
        float h2a[4][4];
        #pragma unroll
        for (int mm=0;mm<4;mm++)
            #pragma unroll
            for (int c=0;c<4;c++) h2a[mm][c] = 0.f;
        #pragma unroll 2
        for (int j4=0;j4<32;j4++){
            float4 xq0 = *(const float4*)(S + 0*128 + j4*4);
            float4 xq1 = *(const float4*)(S + 1*128 + j4*4);
            float4 xq2 = *(const float4*)(S + 2*128 + j4*4);
            float4 xq3 = *(const float4*)(S + 3*128 + j4*4);
            #pragma unroll
            for (int jj=0;jj<4;jj++){
                float4 wv = *(const float4*)(sm + OFF_FW2T + (j4*4+jj)*128 + 4*l);
                float xa0=f4get(xq0,jj), xa1=f4get(xq1,jj), xa2=f4get(xq2,jj), xa3=f4get(xq3,jj);
                h2a[0][0]+=wv.x*xa0; h2a[0][1]+=wv.y*xa0; h2a[0][2]+=wv.z*xa0; h2a[0][3]+=wv.w*xa0;
                h2a[1][0]+=wv.x*xa1; h2a[1][1]+=wv.y*xa1; h2a[1][2]+=wv.z*xa1; h2a[1][3]+=wv.w*xa1;
                h2a[2][0]+=wv.x*xa2; h2a[2][1]+=wv.y*xa2; h2a[2][2]+=wv.z*xa2; h2a[2][3]+=wv.w*xa2;
                h2a[3][0]+=wv.x*xa3; h2a[3][1]+=wv.y*xa3; h2a[3][2]+=wv.z*xa3; h2a[3][3]+=wv.w*xa3;
            }
        }
        {
            float bv2[4] = {FB2H[4*l], FB2H[4*l+1], FB2H[4*l+2], FB2H[4*l+3]};
            const float fb2h2 = SC[9];
            #pragma unroll
            for (int mm=0;mm<4;mm++){
                float axo, r2o;
                blin_nl<4>(h2a[mm], bv2, fb2h2, ax1[mm], false, axo, r2o);
                float fk  = __fdividef(2.0f, 1.0f + r2o);
                float kk2 = fk*fk*r2o;
                float lor = rsqrtf(fmaxf(1.0f - kk2, MINV));
                float cw  = S[SOFF_MASK + mm]*lor;
                float cf  = cw*fk;
                mden += cw;
                #pragma unroll
                for (int c=0;c<4;c++) mnum[c] += cf*h2a[mm][c];
            }
        }
        __syncwarp();
    }

    // ---- neighbor Klein midpoint -> mid (128-d) ----
    float imd = __fdividef(1.0f, fmaxf(mden, MINV));
    float mk4[4]; float s = 0.f;
    #pragma unroll
    for (int c=0;c<4;c++){ mk4[c] = mnum[c]*imd; s += mk4[c]*mk4[c]; }
    float kk2 = wred(s);
    float s2 = __fdividef(1.0f, 1.0f + sqrtf(fmaxf(1.0f - kk2, MINV)));
    float p2 = s2*s2*kk2;
    float spp = 1.0f;
    { float pn = sqrtf(fmaxf(p2, MINV));
      if (pn > MAXN){ spp = __fdividef(MAXN, pn); p2 = MAXN*MAXN; } }
    float cc = s2*spp;
    #pragma unroll
    for (int c=0;c<4;c++) mk4[c] *= cc;
    *(float4*)(S + 4*l) = make_float4(mk4[0], mk4[1], mk4[2], mk4[3]);
    float axmid;
    { float nn = sqrtf(fmaxf(p2, MINV)); axmid = __fdividef(artanh_c(nn), nn); }
    __syncwarp();

    // ---- tail E1: out1 = blinear(mid, gw1, gb1, relu) ----
    float g1v[2] = {0.f, 0.f};
    #pragma unroll 4
    for (int i4=0;i4<32;i4++){
        float4 xs = *(const float4*)(S + i4*4);
        float4 w0 = __ldg((const float4*)(gw1 + (2*l)*128 + i4*4));
        float4 w1 = __ldg((const float4*)(gw1 + (2*l+1)*128 + i4*4));
        g1v[0] += w0.x*xs.x + w0.y*xs.y + w0.z*xs.z + w0.w*xs.w;
        g1v[1] += w1.x*xs.x + w1.y*xs.y + w1.z*xs.z + w1.w*xs.w;
    }
    __syncwarp();
    float axo1, r2o1;
    {
        float bvg1[2] = {GB1H[2*l], GB1H[2*l+1]};
        blin_nl<2>(g1v, bvg1, SC[10], axmid, true, axo1, r2o1);
    }
    *(float2*)(S + 2*l) = make_float2(g1v[0], g1v[1]);
    __syncwarp();

    // ---- tail E2: out = blinear(out1, gw2, gb2) ----
    float g2v[2] = {0.f, 0.f};
    #pragma unroll 4
    for (int i4=0;i4<16;i4++){
        float4 xs = *(const float4*)(S + i4*4);
        float4 w0 = __ldg((const float4*)(gw2 + (2*l)*64 + i4*4));
        float4 w1 = __ldg((const float4*)(gw2 + (2*l+1)*64 + i4*4));
        g2v[0] += w0.x*xs.x + w0.y*xs.y + w0.z*xs.z + w0.w*xs.w;
        g2v[1] += w1.x*xs.x + w1.y*xs.y + w1.z*xs.z + w1.w*xs.w;
    }
    float axo2, r2o2;
    {
        float bvg2[2] = {GB2H[2*l], GB2H[2*l+1]};
        blin_nl<2>(g2v, bvg2, SC[11], axo1, false, axo2, r2o2);
    }
    *(float2*)(out + node*64 + 2*l) = make_float2(g2v[0], g2v[1]);
}

extern "C" void kernel_launch(void* const* d_in, const int* in_sizes, int n_in,
                              void* d_out, int out_size){
    const float* x       = (const float*)d_in[0];
    const int*   nei     = (const int*)  d_in[1];
    const float* neimask = (const float*)d_in[2];
    const float* kt      = (const float*)d_in[3];
    const float* lin_w   = (const float*)d_in[4];
    const float* lin_b   = (const float*)d_in[5];
    const float* fw1     = (const float*)d_in[6];
    const float* fb1     = (const float*)d_in[7];
    const float* fw2     = (const float*)d_in[8];
    const float* fb2     = (const float*)d_in[9];
    const float* gw1     = (const float*)d_in[10];
    const float* gb1     = (const float*)d_in[11];
    const float* gw2     = (const float*)d_in[12];
    const float* gb2     = (const float*)d_in[13];
    float* out = (float*)d_out;
    const int N = in_sizes[0]/64;

    cudaFuncSetAttribute(kp_main, cudaFuncAttributeMaxDynamicSharedMemorySize, SMEM_BYTES);
    prep_kernel<<<1, 256>>>(kt, lin_b, fb1, fb2, gb1, gb2);
    kp_main<<<(N + NWARP - 1)/NWARP, NTHR, SMEM_BYTES>>>(x, nei, neimask, lin_w, fw1, fw2, gw1, gw2, out, N);
}

// round 8
// speedup vs baseline: 1.4132x; 1.1464x over previous
#include <cuda_runtime.h>

#define FULLMASK 0xffffffffu
#define MINV 1e-12f
#define EPSV 1e-6f
#define MAXN (1.0f - 1e-5f)
#define KPI  (1.0f/0.66f)

#define NWARP 28
#define NTHR  (NWARP*32)

// shared layout (float offsets)
#define OFF_W4    0            // [2][64][128] packed lin_w
#define OFF_FW1T  16384        // [64][128]
#define OFF_FW2T  24576        // [128][128]
#define OFF_CONST 40960        // 912 floats
#define OFF_STAGE 41872
#define WSTRIDE   544
#define SOFF_WKM  512          // 16: wkm[mm*4+k]
#define SOFF_AARR 528          // 4
#define SOFF_MASK 532          // 4
#define SOFF_XK   536          // 4
#define SMEM_FLOATS (OFF_STAGE + NWARP*WSTRIDE)
#define SMEM_BYTES  (SMEM_FLOATS*4)

__device__ float g_const[1024];
// 0 klp[4][64], 256 hb[4][64], 512 fb1h[128], 640 fb2h[128], 768 gb1h[64], 832 gb2h[64], 896 scal[12]

__device__ __forceinline__ float wred(float v){
    v += __shfl_xor_sync(FULLMASK, v, 16);
    v += __shfl_xor_sync(FULLMASK, v, 8);
    v += __shfl_xor_sync(FULLMASK, v, 4);
    v += __shfl_xor_sync(FULLMASK, v, 2);
    v += __shfl_xor_sync(FULLMASK, v, 1);
    return v;
}
__device__ __forceinline__ float tanh_pos(float xx){
    float e = __expf(-2.0f*xx);
    return __fdividef(1.0f - e, 1.0f + e);
}
__device__ __forceinline__ float artanh_c(float xx){
    xx = fminf(fmaxf(xx, -1.0f + EPSV), 1.0f - EPSV);
    return 0.5f*__logf(__fdividef(1.0f + xx, 1.0f - xx));
}
__device__ __forceinline__ float f4get(const float4 v, int i){
    return (i==0) ? v.x : (i==1) ? v.y : (i==2) ? v.z : v.w;
}

template<int V>
__device__ __forceinline__ void emap(const float* __restrict__ b, float* __restrict__ dst,
                                     float* __restrict__ n2dst, bool doproj){
    int l = threadIdx.x & 31;
    float u[V]; float s = 0.f;
    #pragma unroll
    for (int c=0;c<V;c++){ u[c] = b[V*l+c]; s += u[c]*u[c]; }
    float n2 = wred(s);
    float n  = sqrtf(fmaxf(n2, MINV));
    float f  = __fdividef(tanh_pos(n), n);
    float h2 = f*f*n2;
    if (doproj){
        float pn = sqrtf(fmaxf(h2, MINV));
        if (pn > MAXN){ f *= __fdividef(MAXN, pn); h2 = MAXN*MAXN; }
    }
    #pragma unroll
    for (int c=0;c<V;c++) dst[V*l+c] = f*u[c];
    if (l == 0) *n2dst = h2;
}

__global__ void prep_kernel(const float* __restrict__ kt, const float* __restrict__ lin_b,
                            const float* __restrict__ fb1, const float* __restrict__ fb2,
                            const float* __restrict__ gb1, const float* __restrict__ gb2){
    int w = threadIdx.x >> 5;
    if (w < 4){
        emap<2>(kt + w*64,    g_const + w*64,       g_const + 896 + w, false);
        emap<2>(lin_b + w*64, g_const + 256 + w*64, g_const + 900 + w, true);
    } else if (w == 4) emap<4>(fb1, g_const + 512, g_const + 904, true);
    else if (w == 5)   emap<4>(fb2, g_const + 640, g_const + 905, true);
    else if (w == 6)   emap<2>(gb1, g_const + 768, g_const + 906, true);
    else if (w == 7)   emap<2>(gb2, g_const + 832, g_const + 907, true);
}

template<int V>
__device__ __forceinline__ void blin_nl(float* h, const float* bvec, float b2,
                                        float ax_in, bool do_act,
                                        float& out_ax, float& out_n2){
    float s = 0.f;
    #pragma unroll
    for (int c=0;c<V;c++) s += h[c]*h[c];
    float mv2 = wred(s);
    float mvn = sqrtf(fmaxf(mv2, MINV));
    float fac = __fdividef(tanh_pos(mvn*ax_in), mvn);
    float f2  = fac*fac*mv2;
    { float pn = sqrtf(fmaxf(f2, MINV));
      if (pn > MAXN){ fac *= __fdividef(MAXN, pn); f2 = MAXN*MAXN; } }
    float mh = 0.f;
    #pragma unroll
    for (int c=0;c<V;c++) mh += h[c]*bvec[c];
    mh = wred(mh);
    float xy  = fac*mh;
    float A   = 1.0f + 2.0f*xy + b2;
    float B   = 1.0f - f2;
    float D   = fmaxf(1.0f + 2.0f*xy + f2*b2, MINV);
    float idn = __fdividef(1.0f, D);
    float r2  = (A*A*f2 + 2.0f*A*B*xy + B*B*b2)*idn*idn;
    float sp  = 1.0f;
    { float rn = sqrtf(fmaxf(r2, MINV));
      if (rn > MAXN){ sp = __fdividef(MAXN, rn); r2 = MAXN*MAXN; } }
    float cA = sp*idn*A*fac, cB = sp*idn*B;
    #pragma unroll
    for (int c=0;c<V;c++) h[c] = cA*h[c] + cB*bvec[c];
    if (do_act){
        float rn = sqrtf(fmaxf(r2, MINV));
        float lm = __fdividef(artanh_c(rn), rn);
        float t = 0.f;
        #pragma unroll
        for (int c=0;c<V;c++){ float u = fmaxf(h[c],0.f)*lm; h[c]=u; t += u*u; }
        float t2 = wred(t);
        float tn = sqrtf(fmaxf(t2, MINV));
        float ef = __fdividef(tanh_pos(tn), tn);
        float o2 = ef*ef*t2;
        float so = 1.0f;
        { float on = sqrtf(fmaxf(o2, MINV));
          if (on > MAXN){ so = __fdividef(MAXN, on); o2 = MAXN*MAXN; } }
        float cc = ef*so;
        #pragma unroll
        for (int c=0;c<V;c++) h[c] *= cc;
        r2 = o2;
    }
    out_n2 = r2;
    float nn = sqrtf(fmaxf(r2, MINV));
    out_ax = __fdividef(artanh_c(nn), nn);
}

__global__ void __launch_bounds__(NTHR, 1)
kp_main(const float* __restrict__ x, const int* __restrict__ nei,
        const float* __restrict__ neimask, const float* __restrict__ lin_w,
        const float* __restrict__ fw1, const float* __restrict__ fw2,
        const float* __restrict__ gw1, const float* __restrict__ gw2,
        float* __restrict__ out, int N)
{
    extern __shared__ float sm[];
    const int tid = threadIdx.x, wid = tid >> 5, l = tid & 31;

    for (int i = tid; i < 16384; i += NTHR){
        int p = i >> 13, r = i & 8191, row = r >> 7, q = r & 127;
        int lane = q >> 2, c = q & 3;
        int k = 2*p + (c >> 1), o = 2*lane + (c & 1);
        sm[OFF_W4 + i] = lin_w[k*4096 + o*64 + row];
    }
    for (int i = tid; i < 8192; i += NTHR){
        int o = i >> 6, ii = i & 63;
        sm[OFF_FW1T + ii*128 + o] = fw1[i];
    }
    for (int i = tid; i < 16384; i += NTHR){
        int o = i >> 7, ii = i & 127;
        sm[OFF_FW2T + ii*128 + o] = fw2[i];
    }
    for (int i = tid; i < 908; i += NTHR) sm[OFF_CONST + i] = g_const[i];
    __syncthreads();

    const int node = blockIdx.x*NWARP + wid;
    if (node >= N) return;

    float* S = sm + OFF_STAGE + wid*WSTRIDE;
    const float* KLP  = sm + OFF_CONST;
    const float* HB   = KLP + 256;
    const float* FB1H = KLP + 512;
    const float* FB2H = KLP + 640;
    const float* GB1H = KLP + 768;
    const float* GB2H = KLP + 832;
    const float* SC   = KLP + 896;

    // center point
    float2 xv = *(const float2*)(x + node*64 + 2*l);
    float x2 = wred(xv.x*xv.x + xv.y*xv.y);
    { float n = sqrtf(fmaxf(x2, MINV));
      if (n > MAXN){ float s = __fdividef(MAXN, n); xv.x*=s; xv.y*=s; x2 = MAXN*MAXN; } }

    // center-kernel dots (node-invariant), stashed in per-warp scratch
    {
        float xk[4];
        #pragma unroll
        for (int k=0;k<4;k++){
            float2 kp = *(const float2*)(KLP + k*64 + 2*l);
            xk[k] = wred(xv.x*kp.x + xv.y*kp.y);
        }
        if (l == 0) *(float4*)(S + SOFF_XK) = make_float4(xk[0], xk[1], xk[2], xk[3]);
    }
    __syncwarp();

    float mnum[4] = {0.f,0.f,0.f,0.f};
    float mden = 0.f;

    for (int g = 0; g < 4; g++){
        // ---- stage A phase 1: gather/proj + warp reductions, deposit into lanes ----
        float d_n2 = 0.f, d_xdn = 0.f, d_nk = 0.f;
        #pragma unroll
        for (int mm=0; mm<4; mm++){
            const int m = g*4 + mm;
            const int idx = __ldg(nei + node*16 + m);
            float2 v = *(const float2*)(x + idx*64 + 2*l);
            float n2 = wred(v.x*v.x + v.y*v.y);
            float nn = sqrtf(fmaxf(n2, MINV));
            if (nn > MAXN){ float s = __fdividef(MAXN, nn); v.x*=s; v.y*=s; n2 = MAXN*MAXN; }
            *(float2*)(S + mm*64 + 2*l) = v;
            float xdn = wred(xv.x*v.x + xv.y*v.y);
            const bool quad = ((l>>2) == mm);
            if (quad){ d_n2 = n2; d_xdn = xdn; }
            #pragma unroll
            for (int k=0;k<4;k++){
                float2 kp = *(const float2*)(KLP + k*64 + 2*l);
                float nk = wred(v.x*kp.x + v.y*kp.y);
                if (quad && (l&3)==k) d_nk = nk;
            }
        }
        // ---- stage A phase 2: one lane-parallel chain; lane j=mm*4+k handles (mm,k) ----
        {
            const int mmj = (l >> 2) & 3, kj = l & 3;
            float xkj   = S[SOFF_XK + kj];
            float klp2j = SC[kj];
            float a   = 1.0f - 2.0f*d_xdn + d_n2;
            float b   = 1.0f - x2;
            float den = fmaxf(1.0f - 2.0f*d_xdn + x2*d_n2, MINV);
            float idn = __fdividef(1.0f, den);
            float x02 = (a*a*x2 - 2.0f*a*b*d_xdn + b*b*d_n2)*idn*idn;
            float s0  = 1.0f;
            { float n0 = sqrtf(fmaxf(x02, MINV));
              if (n0 > MAXN){ s0 = __fdividef(MAXN, n0); x02 = MAXN*MAXN; } }
            float x0k = (-a*xkj + b*d_nk)*idn*s0;
            float A = 1.0f - 2.0f*x0k + klp2j;
            float B = 1.0f - x02;
            float D = fmaxf(1.0f - 2.0f*x0k + x02*klp2j, MINV);
            float iD = __fdividef(1.0f, D);
            float nsq = (A*A*x02 - 2.0f*A*B*x0k + B*B*klp2j)*iD*iD;
            float nd = sqrtf(fmaxf(nsq, MINV));
            float dd = 2.0f*artanh_c(nd);
            float wv = fmaxf(0.f, 1.0f - dd*KPI);
            float sw = wv + __shfl_xor_sync(FULLMASK, wv, 1);
            sw += __shfl_xor_sync(FULLMASK, sw, 2);
            float isw = __fdividef(1.0f, fmaxf(sw, MINV));
            if (l < 16){
                S[SOFF_WKM + l] = wv*isw;
                if (kj == 0){
                    float nn2 = sqrtf(fmaxf(d_n2, MINV));
                    S[SOFF_AARR + mmj] = __fdividef(artanh_c(nn2), nn2);
                    S[SOFF_MASK + mmj] = __ldg(neimask + node*16 + g*4 + mmj);
                }
            }
        }
        __syncwarp();

        // ---- stage B: two k-pair passes; lane-parallel epilogue ----
        float kn0[4], kn1[4], kdn[4];
        #pragma unroll
        for (int mm=0;mm<4;mm++){ kn0[mm]=0.f; kn1[mm]=0.f; kdn[mm]=0.f; }
        #pragma unroll 1
        for (int p=0;p<2;p++){
            float acc[2][4][2];
            #pragma unroll
            for (int kk=0;kk<2;kk++)
                #pragma unroll
                for (int mm=0;mm<4;mm++){ acc[kk][mm][0]=0.f; acc[kk][mm][1]=0.f; }
            #pragma unroll 2
            for (int j4=0;j4<16;j4++){
                float4 xq0 = *(const float4*)(S + 0*64 + j4*4);
                float4 xq1 = *(const float4*)(S + 1*64 + j4*4);
                float4 xq2 = *(const float4*)(S + 2*64 + j4*4);
                float4 xq3 = *(const float4*)(S + 3*64 + j4*4);
                #pragma unroll
                for (int jj=0;jj<4;jj++){
                    float4 w4 = *(const float4*)(sm + OFF_W4 + p*8192 + (j4*4+jj)*128 + 4*l);
                    float xa0=f4get(xq0,jj), xa1=f4get(xq1,jj), xa2=f4get(xq2,jj), xa3=f4get(xq3,jj);
                    acc[0][0][0] += w4.x*xa0; acc[0][0][1] += w4.y*xa0;
                    acc[1][0][0] += w4.z*xa0; acc[1][0][1] += w4.w*xa0;
                    acc[0][1][0] += w4.x*xa1; acc[0][1][1] += w4.y*xa1;
                    acc[1][1][0] += w4.z*xa1; acc[1][1][1] += w4.w*xa1;
                    acc[0][2][0] += w4.x*xa2; acc[0][2][1] += w4.y*xa2;
                    acc[1][2][0] += w4.z*xa2; acc[1][2][1] += w4.w*xa2;
                    acc[0][3][0] += w4.x*xa3; acc[0][3][1] += w4.y*xa3;
                    acc[1][3][0] += w4.z*xa3; acc[1][3][1] += w4.w*xa3;
                }
            }
            // epilogue phase 1: reductions + lane deposits (lane j = kk*4+mm)
            float2 hbv0 = *(const float2*)(HB + (2*p+0)*64 + 2*l);
            float2 hbv1 = *(const float2*)(HB + (2*p+1)*64 + 2*l);
            float d_mx2 = 0.f, d_mh = 0.f;
            #pragma unroll
            for (int kk=0;kk<2;kk++){
                float2 hbv = kk ? hbv1 : hbv0;
                #pragma unroll
                for (int mm=0;mm<4;mm++){
                    float a0=acc[kk][mm][0], a1=acc[kk][mm][1];
                    float mx2 = wred(a0*a0 + a1*a1);
                    float mh  = wred(a0*hbv.x + a1*hbv.y);
                    if (l == kk*4+mm){ d_mx2 = mx2; d_mh = mh; }
                }
            }
            // epilogue phase 2: one lane-parallel chain (lanes 0-7 meaningful)
            float c1, c2, cwv;
            {
                const int kkj = (l >> 2) & 1, mmj = l & 3;
                const int kj = 2*p + kkj;
                float aa   = S[SOFF_AARR + mmj];
                float hb2k = SC[4 + kj];
                float wkmv = S[SOFF_WKM + mmj*4 + kj];
                float mxn = sqrtf(fmaxf(d_mx2, MINV));
                float fac = __fdividef(tanh_pos(mxn*aa), mxn);
                float f2  = fac*fac*d_mx2;
                { float pn = sqrtf(fmaxf(f2, MINV));
                  if (pn > MAXN){ fac *= __fdividef(MAXN, pn); f2 = MAXN*MAXN; } }
                float xy = fac*d_mh;
                float A = 1.0f + 2.0f*xy + hb2k;
                float B = 1.0f - f2;
                float D = fmaxf(1.0f + 2.0f*xy + f2*hb2k, MINV);
                float iD = __fdividef(1.0f, D);
                float r2 = (A*A*f2 + 2.0f*A*B*xy + B*B*hb2k)*iD*iD;
                float sp = 1.0f;
                { float rn = sqrtf(fmaxf(r2, MINV));
                  if (rn > MAXN){ sp = __fdividef(MAXN, rn); r2 = MAXN*MAXN; } }
                float fk  = __fdividef(2.0f, 1.0f + r2);
                float kk2 = fk*fk*r2;
                float lor = rsqrtf(fmaxf(1.0f - kk2, MINV));
                cwv = wkmv*lor;
                float cf  = cwv*fk*sp*iD;
                c1 = cf*A*fac;
                c2 = cf*B;
            }
            // epilogue phase 3: broadcast coefficients, accumulate Klein sums
            #pragma unroll
            for (int kk=0;kk<2;kk++){
                float2 hbv = kk ? hbv1 : hbv0;
                #pragma unroll
                for (int mm=0;mm<4;mm++){
                    const int j = kk*4+mm;
                    float c1j = __shfl_sync(FULLMASK, c1, j);
                    float c2j = __shfl_sync(FULLMASK, c2, j);
                    float cwj = __shfl_sync(FULLMASK, cwv, j);
                    kn0[mm] += c1j*acc[kk][mm][0] + c2j*hbv.x;
                    kn1[mm] += c1j*acc[kk][mm][1] + c2j*hbv.y;
                    kdn[mm] += cwj;
                }
            }
        }
        __syncwarp();

        // ---- stage C: Klein midpoint normalize -> agg ----
        float axagg[4];
        #pragma unroll
        for (int mm=0;mm<4;mm++){
            float ikd = __fdividef(1.0f, fmaxf(kdn[mm], MINV));
            float k0 = kn0[mm]*ikd, k1 = kn1[mm]*ikd;
            float kk2 = wred(k0*k0 + k1*k1);
            float s2 = __fdividef(1.0f, 1.0f + sqrtf(fmaxf(1.0f - kk2, MINV)));
            float p0 = s2*k0, p1 = s2*k1;
            float p2 = s2*s2*kk2;
            float spp = 1.0f;
            { float pn = sqrtf(fmaxf(p2, MINV));
              if (pn > MAXN){ spp = __fdividef(MAXN, pn); p2 = MAXN*MAXN; } }
            p0 *= spp; p1 *= spp;
            { float nn = sqrtf(fmaxf(p2, MINV)); axagg[mm] = __fdividef(artanh_c(nn), nn); }
            *(float2*)(S + mm*64 + 2*l) = make_float2(p0, p1);
        }
        __syncwarp();

        // ---- stage D1: h1 = blinear(agg, fw1, fb1, relu) ----
        float h1[4][4];
        #pragma unroll
        for (int mm=0;mm<4;mm++)
            #pragma unroll
            for (int c=0;c<4;c++) h1[mm][c] = 0.f;
        #pragma unroll 2
        for (int j4=0;j4<16;j4++){
            float4 xq0 = *(const float4*)(S + 0*64 + j4*4);
            float4 xq1 = *(const float4*)(S + 1*64 + j4*4);
            float4 xq2 = *(const float4*)(S + 2*64 + j4*4);
            float4 xq3 = *(const float4*)(S + 3*64 + j4*4);
            #pragma unroll
            for (int jj=0;jj<4;jj++){
                float4 wv = *(const float4*)(sm + OFF_FW1T + (j4*4+jj)*128 + 4*l);
                float xa0=f4get(xq0,jj), xa1=f4get(xq1,jj), xa2=f4get(xq2,jj), xa3=f4get(xq3,jj);
                h1[0][0]+=wv.x*xa0; h1[0][1]+=wv.y*xa0; h1[0][2]+=wv.z*xa0; h1[0][3]+=wv.w*xa0;
                h1[1][0]+=wv.x*xa1; h1[1][1]+=wv.y*xa1; h1[1][2]+=wv.z*xa1; h1[1][3]+=wv.w*xa1;
                h1[2][0]+=wv.x*xa2; h1[2][1]+=wv.y*xa2; h1[2][2]+=wv.z*xa2; h1[2][3]+=wv.w*xa2;
                h1[3][0]+=wv.x*xa3; h1[3][1]+=wv.y*xa3; h1[3][2]+=wv.z*xa3; h1[3][3]+=wv.w*xa3;
            }
        }
        __syncwarp();
        float ax1[4];
        {
            float bv1[4] = {FB1H[4*l], FB1H[4*l+1], FB1H[4*l+2], FB1H[4*l+3]};
            const float fb1h2 = SC[8];
            #pragma unroll
            for (int mm=0;mm<4;mm++){
                float n2o;
                blin_nl<4>(h1[mm], bv1, fb1h2, axagg[mm], true, ax1[mm], n2o);
                *(float4*)(S + mm*128 + 4*l) = make_float4(h1[mm][0], h1[mm][1], h1[mm][2], h1[mm][3]);
            }
        }
        __syncwarp();

        // ---- stage D2: h2 = blinear(h1, fw2, fb2) + neighbor Klein accumulation ----
        float h2a[4][4];
        #pragma unroll
        for (int mm=0;mm<4;mm++)
            #pragma unroll
            for (int c=0;c<4;c++) h2a[mm][c] = 0.f;
        #pragma unroll 2
        for (int j4=0;j4<32;j4++){
            float4 xq0 = *(const float4*)(S + 0*128 + j4*4);
            float4 xq1 = *(const float4*)(S + 1*128 + j4*4);
            float4 xq2 = *(const float4*)(S + 2*128 + j4*4);
            float4 xq3 = *(const float4*)(S + 3*128 + j4*4);
            #pragma unroll
            for (int jj=0;jj<4;jj++){
                float4 wv = *(const float4*)(sm + OFF_FW2T + (j4*4+jj)*128 + 4*l);
                float xa0=f4get(xq0,jj), xa1=f4get(xq1,jj), xa2=f4get(xq2,jj), xa3=f4get(xq3,jj);
                h2a[0][0]+=wv.x*xa0; h2a[0][1]+=wv.y*xa0; h2a[0][2]+=wv.z*xa0; h2a[0][3]+=wv.w*xa0;
                h2a[1][0]+=wv.x*xa1; h2a[1][1]+=wv.y*xa1; h2a[1][2]+=wv.z*xa1; h2a[1][3]+=wv.w*xa1;
                h2a[2][0]+=wv.x*xa2; h2a[2][1]+=wv.y*xa2; h2a[2][2]+=wv.z*xa2; h2a[2][3]+=wv.w*xa2;
                h2a[3][0]+=wv.x*xa3; h2a[3][1]+=wv.y*xa3; h2a[3][2]+=wv.z*xa3; h2a[3][3]+=wv.w*xa3;
            }
        }
        {
            float bv2[4] = {FB2H[4*l], FB2H[4*l+1], FB2H[4*l+2], FB2H[4*l+3]};
            const float fb2h2 = SC[9];
            #pragma unroll
            for (int mm=0;mm<4;mm++){
                float axo, r2o;
                blin_nl<4>(h2a[mm], bv2, fb2h2, ax1[mm], false, axo, r2o);
                float fk  = __fdividef(2.0f, 1.0f + r2o);
                float kk2 = fk*fk*r2o;
                float lor = rsqrtf(fmaxf(1.0f - kk2, MINV));
                float cw  = S[SOFF_MASK + mm]*lor;
                float cf  = cw*fk;
                mden += cw;
                #pragma unroll
                for (int c=0;c<4;c++) mnum[c] += cf*h2a[mm][c];
            }
        }
        __syncwarp();
    }

    // ---- neighbor Klein midpoint -> mid (128-d) ----
    float imd = __fdividef(1.0f, fmaxf(mden, MINV));
    float mk4[4]; float s = 0.f;
    #pragma unroll
    for (int c=0;c<4;c++){ mk4[c] = mnum[c]*imd; s += mk4[c]*mk4[c]; }
    float kk2 = wred(s);
    float s2 = __fdividef(1.0f, 1.0f + sqrtf(fmaxf(1.0f - kk2, MINV)));
    float p2 = s2*s2*kk2;
    float spp = 1.0f;
    { float pn = sqrtf(fmaxf(p2, MINV));
      if (pn > MAXN){ spp = __fdividef(MAXN, pn); p2 = MAXN*MAXN; } }
    float cc = s2*spp;
    #pragma unroll
    for (int c=0;c<4;c++) mk4[c] *= cc;
    *(float4*)(S + 4*l) = make_float4(mk4[0], mk4[1], mk4[2], mk4[3]);
    float axmid;
    { float nn = sqrtf(fmaxf(p2, MINV)); axmid = __fdividef(artanh_c(nn), nn); }
    __syncwarp();

    // ---- tail E1: out1 = blinear(mid, gw1, gb1, relu) ----
    float g1v[2] = {0.f, 0.f};
    #pragma unroll 4
    for (int i4=0;i4<32;i4++){
        float4 xs = *(const float4*)(S + i4*4);
        float4 w0 = __ldg((const float4*)(gw1 + (2*l)*128 + i4*4));
        float4 w1 = __ldg((const float4*)(gw1 + (2*l+1)*128 + i4*4));
        g1v[0] += w0.x*xs.x + w0.y*xs.y + w0.z*xs.z + w0.w*xs.w;
        g1v[1] += w1.x*xs.x + w1.y*xs.y + w1.z*xs.z + w1.w*xs.w;
    }
    __syncwarp();
    float axo1, r2o1;
    {
        float bvg1[2] = {GB1H[2*l], GB1H[2*l+1]};
        blin_nl<2>(g1v, bvg1, SC[10], axmid, true, axo1, r2o1);
    }
    *(float2*)(S + 2*l) = make_float2(g1v[0], g1v[1]);
    __syncwarp();

    // ---- tail E2: out = blinear(out1, gw2, gb2) ----
    float g2v[2] = {0.f, 0.f};
    #pragma unroll 4
    for (int i4=0;i4<16;i4++){
        float4 xs = *(const float4*)(S + i4*4);
        float4 w0 = __ldg((const float4*)(gw2 + (2*l)*64 + i4*4));
        float4 w1 = __ldg((const float4*)(gw2 + (2*l+1)*64 + i4*4));
        g2v[0] += w0.x*xs.x + w0.y*xs.y + w0.z*xs.z + w0.w*xs.w;
        g2v[1] += w1.x*xs.x + w1.y*xs.y + w1.z*xs.z + w1.w*xs.w;
    }
    float axo2, r2o2;
    {
        float bvg2[2] = {GB2H[2*l], GB2H[2*l+1]};
        blin_nl<2>(g2v, bvg2, SC[11], axo1, false, axo2, r2o2);
    }
    *(float2*)(out + node*64 + 2*l) = make_float2(g2v[0], g2v[1]);
}

extern "C" void kernel_launch(void* const* d_in, const int* in_sizes, int n_in,
                              void* d_out, int out_size){
    const float* x       = (const float*)d_in[0];
    const int*   nei     = (const int*)  d_in[1];
    const float* neimask = (const float*)d_in[2];
    const float* kt      = (const float*)d_in[3];
    const float* lin_w   = (const float*)d_in[4];
    const float* lin_b   = (const float*)d_in[5];
    const float* fw1     = (const float*)d_in[6];
    const float* fb1     = (const float*)d_in[7];
    const float* fw2     = (const float*)d_in[8];
    const float* fb2     = (const float*)d_in[9];
    const float* gw1     = (const float*)d_in[10];
    const float* gb1     = (const float*)d_in[11];
    const float* gw2     = (const float*)d_in[12];
    const float* gb2     = (const float*)d_in[13];
    float* out = (float*)d_out;
    const int N = in_sizes[0]/64;

    cudaFuncSetAttribute(kp_main, cudaFuncAttributeMaxDynamicSharedMemorySize, SMEM_BYTES);
    prep_kernel<<<1, 256>>>(kt, lin_b, fb1, fb2, gb1, gb2);
    kp_main<<<(N + NWARP - 1)/NWARP, NTHR, SMEM_BYTES>>>(x, nei, neimask, lin_w, fw1, fw2, gw1, gw2, out, N);
}